// round 3
// baseline (speedup 1.0000x reference)
#include <cuda_runtime.h>
#include <mma.h>
#include <cstdint>

using namespace nvcuda;

// Problem dims (fixed by the dataset)
#define D_    1024
#define SQ    1024
#define SK    1024
#define BATCH 8
#define NH    8
#define DH    128

#define NEGV  (-4294967295.0f)   // -2^32 + 1

// ---------------- scratch (device globals: no allocation allowed) ----------------
__device__ float g_K[(size_t)BATCH * SK * D_];   // memory @ Wk
__device__ float g_V[(size_t)BATCH * SK * D_];   // memory @ Wv
__device__ float g_Q[(size_t)BATCH * SQ * D_];   // dec @ Wq
__device__ float g_X[(size_t)BATCH * SQ * D_];   // attn @ V (heads concatenated)
__device__ float g_Y[(size_t)BATCH * SQ * D_];   // concat @ Wf
__device__ int   g_mask_kind;                    // 0=int32, 1=byte, 2=float32

// ---------------- reductions ----------------
__device__ __forceinline__ float blockReduceSum(float v) {
    __shared__ float sh[8];
    __syncthreads();
    #pragma unroll
    for (int o = 16; o > 0; o >>= 1) v += __shfl_xor_sync(0xffffffffu, v, o);
    int lane = threadIdx.x & 31, w = threadIdx.x >> 5;
    if (lane == 0) sh[w] = v;
    __syncthreads();
    if (w == 0) {
        float x = (lane < 8) ? sh[lane] : 0.0f;
        #pragma unroll
        for (int o = 4; o > 0; o >>= 1) x += __shfl_xor_sync(0xffffffffu, x, o);
        if (lane == 0) sh[0] = x;
    }
    __syncthreads();
    return sh[0];
}

__device__ __forceinline__ float blockReduceMax(float v) {
    __shared__ float sh[8];
    __syncthreads();
    #pragma unroll
    for (int o = 16; o > 0; o >>= 1) v = fmaxf(v, __shfl_xor_sync(0xffffffffu, v, o));
    int lane = threadIdx.x & 31, w = threadIdx.x >> 5;
    if (lane == 0) sh[w] = v;
    __syncthreads();
    if (w == 0) {
        float x = (lane < 8) ? sh[lane] : -3.4e38f;
        #pragma unroll
        for (int o = 4; o > 0; o >>= 1) x = fmaxf(x, __shfl_xor_sync(0xffffffffu, x, o));
        if (lane == 0) sh[0] = x;
    }
    __syncthreads();
    return sh[0];
}

// ---------------- generic batched tf32 wmma GEMM ----------------
// C[z][M,N] = alpha * A[z][M,K] * B[z][K,N] (+ C_old if ACC)
// A row-major. B row-major if !BCOL, else B(k,n) = Bptr[n*ldb + k] (i.e. K stored
// row-major viewed as B^T, used for Q*K^T scores).
// z is decomposed z1 = z / Z2, z2 = z % Z2; pointer offset = z1*s1 + z2*s2.
// Requires: M % 128 == 0, N % 128 == 0, K % 16 == 0, 16B-aligned pointers/lds.

#define BM 128
#define BN 128
#define BK 16
#define BKPAD 20    // 80B stride: multiple of 16B
#define BNPAD 132   // 528B stride: multiple of 16B

template<bool BCOL, bool ACC>
__global__ __launch_bounds__(256)
void gemm_tf32(const float* __restrict__ Abase, long long sA1, long long sA2, int lda,
               const float* __restrict__ Bbase, long long sB1, long long sB2, int ldb,
               float*       __restrict__ Cbase, long long sC1, long long sC2, int ldc,
               int K, int Z2, float alpha)
{
    const int z  = blockIdx.z;
    const int z1 = z / Z2, z2 = z % Z2;
    const float* A = Abase + (size_t)z1 * sA1 + (size_t)z2 * sA2;
    const float* B = Bbase + (size_t)z1 * sB1 + (size_t)z2 * sB2;
    float*       C = Cbase + (size_t)z1 * sC1 + (size_t)z2 * sC2;

    const int m0 = blockIdx.y * BM;
    const int n0 = blockIdx.x * BN;

    __shared__ float As[BM][BKPAD];
    constexpr int BSZ = BCOL ? (BN * BKPAD) : (BK * BNPAD);
    __shared__ float Bs[BSZ];

    const int tid    = threadIdx.x;
    const int wid    = tid >> 5;
    const int warp_m = wid & 3;   // 4 warps along M (32 rows each)
    const int warp_n = wid >> 2;  // 2 warps along N (64 cols each)

    wmma::fragment<wmma::accumulator, 16, 16, 8, float> c[2][4];
    #pragma unroll
    for (int mi = 0; mi < 2; mi++)
        #pragma unroll
        for (int ni = 0; ni < 4; ni++)
            wmma::fill_fragment(c[mi][ni], 0.0f);

    for (int k0 = 0; k0 < K; k0 += BK) {
        // --- stage A tile (128 x 16): 512 float4, 2 per thread ---
        #pragma unroll
        for (int i = 0; i < 2; i++) {
            int f4  = tid + i * 256;
            int row = f4 >> 2;
            int c4  = f4 & 3;
            float4 v = *reinterpret_cast<const float4*>(
                A + (size_t)(m0 + row) * lda + k0 + c4 * 4);
            float* dst = &As[row][c4 * 4];
            dst[0] = v.x; dst[1] = v.y; dst[2] = v.z; dst[3] = v.w;
        }
        // --- stage B tile ---
        if (BCOL) {
            // Bs[n][k], n in [n0, n0+128), k in [k0, k0+16)
            #pragma unroll
            for (int i = 0; i < 2; i++) {
                int f4 = tid + i * 256;
                int n  = f4 >> 2;
                int c4 = f4 & 3;
                float4 v = *reinterpret_cast<const float4*>(
                    B + (size_t)(n0 + n) * ldb + k0 + c4 * 4);
                float* dst = &Bs[n * BKPAD + c4 * 4];
                dst[0] = v.x; dst[1] = v.y; dst[2] = v.z; dst[3] = v.w;
            }
        } else {
            // Bs[k][n], k in [k0, k0+16), n in [n0, n0+128)
            #pragma unroll
            for (int i = 0; i < 2; i++) {
                int f4  = tid + i * 256;
                int row = f4 >> 5;
                int c4  = f4 & 31;
                float4 v = *reinterpret_cast<const float4*>(
                    B + (size_t)(k0 + row) * ldb + n0 + c4 * 4);
                float* dst = &Bs[row * BNPAD + c4 * 4];
                dst[0] = v.x; dst[1] = v.y; dst[2] = v.z; dst[3] = v.w;
            }
        }
        __syncthreads();

        #pragma unroll
        for (int kk = 0; kk < BK; kk += 8) {
            wmma::fragment<wmma::matrix_a, 16, 16, 8, wmma::precision::tf32, wmma::row_major> a[2];
            #pragma unroll
            for (int mi = 0; mi < 2; mi++) {
                wmma::load_matrix_sync(a[mi], &As[warp_m * 32 + mi * 16][kk], BKPAD);
                #pragma unroll
                for (int t = 0; t < a[mi].num_elements; t++)
                    a[mi].x[t] = wmma::__float_to_tf32(a[mi].x[t]);
            }
            if (BCOL) {
                wmma::fragment<wmma::matrix_b, 16, 16, 8, wmma::precision::tf32, wmma::col_major> b[4];
                #pragma unroll
                for (int ni = 0; ni < 4; ni++) {
                    wmma::load_matrix_sync(b[ni], &Bs[(warp_n * 64 + ni * 16) * BKPAD + kk], BKPAD);
                    #pragma unroll
                    for (int t = 0; t < b[ni].num_elements; t++)
                        b[ni].x[t] = wmma::__float_to_tf32(b[ni].x[t]);
                }
                #pragma unroll
                for (int mi = 0; mi < 2; mi++)
                    #pragma unroll
                    for (int ni = 0; ni < 4; ni++)
                        wmma::mma_sync(c[mi][ni], a[mi], b[ni], c[mi][ni]);
            } else {
                wmma::fragment<wmma::matrix_b, 16, 16, 8, wmma::precision::tf32, wmma::row_major> b[4];
                #pragma unroll
                for (int ni = 0; ni < 4; ni++) {
                    wmma::load_matrix_sync(b[ni], &Bs[kk * BNPAD + warp_n * 64 + ni * 16], BNPAD);
                    #pragma unroll
                    for (int t = 0; t < b[ni].num_elements; t++)
                        b[ni].x[t] = wmma::__float_to_tf32(b[ni].x[t]);
                }
                #pragma unroll
                for (int mi = 0; mi < 2; mi++)
                    #pragma unroll
                    for (int ni = 0; ni < 4; ni++)
                        wmma::mma_sync(c[mi][ni], a[mi], b[ni], c[mi][ni]);
            }
        }
        __syncthreads();
    }

    // --- epilogue ---
    #pragma unroll
    for (int mi = 0; mi < 2; mi++) {
        #pragma unroll
        for (int ni = 0; ni < 4; ni++) {
            float* Cp = C + (size_t)(m0 + warp_m * 32 + mi * 16) * ldc
                          + n0 + warp_n * 64 + ni * 16;
            #pragma unroll
            for (int t = 0; t < c[mi][ni].num_elements; t++)
                c[mi][ni].x[t] *= alpha;
            if (ACC) {
                wmma::fragment<wmma::accumulator, 16, 16, 8, float> old;
                wmma::load_matrix_sync(old, Cp, ldc, wmma::mem_row_major);
                #pragma unroll
                for (int t = 0; t < c[mi][ni].num_elements; t++)
                    c[mi][ni].x[t] += old.x[t];
            }
            wmma::store_matrix_sync(Cp, c[mi][ni], ldc, wmma::mem_row_major);
        }
    }
}

// ---------------- mask dtype detection ----------------
// Values are 0/1. int32 -> every u32 word is 0 or 1. uint8 -> words are 4 packed
// 0/1 bytes (non-{0,1} words certain within 2048 words at p=0.5). float32 -> words
// are 0 or 0x3F800000. Deterministic: same input -> same flag, every launch.
__global__ void detect_mask_kernel(const unsigned* __restrict__ m) {
    __shared__ int votes[2];  // [0]=byte, [1]=float
    if (threadIdx.x < 2) votes[threadIdx.x] = 0;
    __syncthreads();
    for (int i = threadIdx.x; i < 2048; i += blockDim.x) {
        unsigned w = m[i];
        if (w > 1u) {
            if (w == 0x3F800000u) atomicOr(&votes[1], 1);
            else                  atomicOr(&votes[0], 1);
        }
    }
    __syncthreads();
    if (threadIdx.x == 0)
        g_mask_kind = votes[0] ? 1 : (votes[1] ? 2 : 0);
}

// ---------------- masked softmax + query-mask, in-place on attns ----------------
// One block per (head*B + b, q) row of 1024 scores.
__global__ __launch_bounds__(256)
void softmax_kernel(float* __restrict__ attns,
                    const void* __restrict__ mask,
                    const float* __restrict__ qmask)
{
    const int r  = blockIdx.x;           // 0 .. 64*1024-1
    const int q  = r & (SQ - 1);
    const int hb = r >> 10;
    const int b  = hb & (BATCH - 1);
    float* row = attns + (size_t)r * SK;
    const size_t mbase = ((size_t)b * SQ + q) * (size_t)SK;
    const int t = threadIdx.x;
    const int kind = g_mask_kind;

    float v[4];
    #pragma unroll
    for (int j = 0; j < 4; j++) {
        int idx = t + j * 256;
        bool mm;
        if (kind == 0)      mm = ((const int*)mask)[mbase + idx] != 0;
        else if (kind == 1) mm = ((const unsigned char*)mask)[mbase + idx] != 0;
        else                mm = ((const float*)mask)[mbase + idx] != 0.0f;
        v[j] = mm ? NEGV : row[idx];
    }
    float mx = fmaxf(fmaxf(v[0], v[1]), fmaxf(v[2], v[3]));
    mx = blockReduceMax(mx);

    float p[4], s = 0.0f;
    #pragma unroll
    for (int j = 0; j < 4; j++) { p[j] = __expf(v[j] - mx); s += p[j]; }
    s = blockReduceSum(s);

    const float scale = qmask[b * SQ + q] / s;
    #pragma unroll
    for (int j = 0; j < 4; j++) {
        int idx = t + j * 256;
        row[idx] = p[j] * scale;
    }
}

// ---------------- residual + bias + LayerNorm ----------------
__global__ __launch_bounds__(256)
void ln_kernel(const float* __restrict__ y, const float* __restrict__ dec,
               const float* __restrict__ bf, const float* __restrict__ gamma,
               const float* __restrict__ beta, float* __restrict__ out)
{
    const size_t base = (size_t)blockIdx.x * D_;
    const int t = threadIdx.x;
    float x[4];
    float s = 0.0f, ss = 0.0f;
    #pragma unroll
    for (int j = 0; j < 4; j++) {
        int idx = t + j * 256;
        x[j] = y[base + idx] + bf[idx] + dec[base + idx];
        s += x[j];
        ss += x[j] * x[j];
    }
    s  = blockReduceSum(s);
    ss = blockReduceSum(ss);
    const float mu   = s * (1.0f / D_);
    const float var  = ss * (1.0f / D_) - mu * mu;
    const float rstd = rsqrtf(var + 1e-5f);
    #pragma unroll
    for (int j = 0; j < 4; j++) {
        int idx = t + j * 256;
        out[base + idx] = (x[j] - mu) * rstd * gamma[idx] + beta[idx];
    }
}

// ---------------- launcher ----------------
extern "C" void kernel_launch(void* const* d_in, const int* in_sizes, int n_in,
                              void* d_out, int out_size)
{
    (void)in_sizes; (void)n_in; (void)out_size;
    const float* memory = (const float*)d_in[0];
    const float* dec    = (const float*)d_in[1];
    const float* qmask  = (const float*)d_in[2];
    const float* Wk     = (const float*)d_in[3];
    const float* Wv     = (const float*)d_in[4];
    const float* Wq     = (const float*)d_in[5];
    const float* Wf     = (const float*)d_in[6];
    const float* bf     = (const float*)d_in[7];
    const float* gamma  = (const float*)d_in[8];
    const float* beta   = (const float*)d_in[9];
    const void*  mask   = d_in[10];

    float* out_x = (float*)d_out;
    float* attns = out_x + (size_t)BATCH * SQ * D_;   // x first, then attns

    float *gK, *gV, *gQ, *gX, *gY;
    cudaGetSymbolAddress((void**)&gK, g_K);
    cudaGetSymbolAddress((void**)&gV, g_V);
    cudaGetSymbolAddress((void**)&gQ, g_Q);
    cudaGetSymbolAddress((void**)&gX, g_X);
    cudaGetSymbolAddress((void**)&gY, g_Y);

    const dim3 blk(256);
    const long long SqD = (long long)SQ * D_;
    const long long SkD = (long long)SK * D_;
    const long long SqSk = (long long)SQ * SK;
    const float inv_sqrt_dh = 0.08838834764831843f;  // 1/sqrt(128)

    // 1) projections: [8192,1024] x [1024,1024]
    gemm_tf32<false, false><<<dim3(D_ / BN, (BATCH * SK) / BM, 1), blk>>>(
        memory, 0, 0, D_, Wk, 0, 0, D_, gK, 0, 0, D_, D_, 1, 1.0f);
    gemm_tf32<false, false><<<dim3(D_ / BN, (BATCH * SK) / BM, 1), blk>>>(
        memory, 0, 0, D_, Wv, 0, 0, D_, gV, 0, 0, D_, D_, 1, 1.0f);
    gemm_tf32<false, false><<<dim3(D_ / BN, (BATCH * SQ) / BM, 1), blk>>>(
        dec, 0, 0, D_, Wq, 0, 0, D_, gQ, 0, 0, D_, D_, 1, 1.0f);

    // 2) scores: per (head,b): S = Q_hb @ K_hb^T / sqrt(dh)  -> attns region (raw)
    //    z = head*BATCH + b; A = Q + head*DH + b*SqD; B(col) = K + head*DH + b*SkD
    gemm_tf32<true, false><<<dim3(SK / BN, SQ / BM, NH * BATCH), blk>>>(
        gQ, DH, SqD, D_,
        gK, DH, SkD, D_,
        attns, (long long)BATCH * SqSk, SqSk, SK,
        DH, BATCH, inv_sqrt_dh);

    // 3) mask dtype detect + masked softmax + query-mask (in-place in d_out)
    detect_mask_kernel<<<1, 256>>>((const unsigned*)mask);
    softmax_kernel<<<NH * BATCH * SQ, 256>>>(attns, mask, qmask);

    // 4) attn @ V: per (head,b): [1024,1024] x [1024,128] -> gX (heads concat)
    gemm_tf32<false, false><<<dim3(DH / BN, SQ / BM, NH * BATCH), blk>>>(
        attns, (long long)BATCH * SqSk, SqSk, SK,
        gV, DH, SkD, D_,
        gX, DH, SqD, D_,
        SK, BATCH, 1.0f);

    // 5) y = dec @ Wf[:D] ; y += x_attn @ Wf[D:]
    gemm_tf32<false, false><<<dim3(D_ / BN, (BATCH * SQ) / BM, 1), blk>>>(
        dec, 0, 0, D_, Wf, 0, 0, D_, gY, 0, 0, D_, D_, 1, 1.0f);
    gemm_tf32<false, true><<<dim3(D_ / BN, (BATCH * SQ) / BM, 1), blk>>>(
        gX, 0, 0, D_, Wf + (size_t)D_ * D_, 0, 0, D_, gY, 0, 0, D_, D_, 1, 1.0f);

    // 6) residual + bias + LayerNorm -> x output
    ln_kernel<<<BATCH * SQ, 256>>>(gY, dec, bf, gamma, beta, out_x);
}

// round 5
// speedup vs baseline: 1.2947x; 1.2947x over previous
#include <cuda_runtime.h>
#include <mma.h>
#include <cstdint>

using namespace nvcuda;

// Problem dims (fixed by the dataset)
#define D_    1024
#define SQ    1024
#define SK    1024
#define BATCH 8
#define NH    8
#define DH    128

#define NEGV  (-4294967295.0f)   // -2^32 + 1

// ---------------- scratch (device globals: no allocation allowed) ----------------
__device__ float g_K[(size_t)BATCH * SK * D_];   // memory @ Wk
__device__ float g_V[(size_t)BATCH * SK * D_];   // memory @ Wv
__device__ float g_Q[(size_t)BATCH * SQ * D_];   // dec @ Wq
__device__ float g_X[(size_t)BATCH * SQ * D_];   // attn @ V (heads concatenated)
__device__ float g_Y[(size_t)BATCH * SQ * D_];   // concat @ Wf
__device__ int   g_mask_kind;                    // 0=int32, 1=byte, 2=float32

// ---------------- cp.async helpers ----------------
__device__ __forceinline__ void cp16(void* smem_dst, const void* gsrc) {
    uint32_t s = (uint32_t)__cvta_generic_to_shared(smem_dst);
    asm volatile("cp.async.cg.shared.global [%0], [%1], 16;\n" :: "r"(s), "l"(gsrc));
}
__device__ __forceinline__ void cp_commit() {
    asm volatile("cp.async.commit_group;\n");
}
__device__ __forceinline__ void cp_wait1() {
    asm volatile("cp.async.wait_group 1;\n");
}

// ---------------- reductions ----------------
__device__ __forceinline__ float blockReduceSum(float v) {
    __shared__ float sh[8];
    __syncthreads();
    #pragma unroll
    for (int o = 16; o > 0; o >>= 1) v += __shfl_xor_sync(0xffffffffu, v, o);
    int lane = threadIdx.x & 31, w = threadIdx.x >> 5;
    if (lane == 0) sh[w] = v;
    __syncthreads();
    if (w == 0) {
        float x = (lane < 8) ? sh[lane] : 0.0f;
        #pragma unroll
        for (int o = 4; o > 0; o >>= 1) x += __shfl_xor_sync(0xffffffffu, x, o);
        if (lane == 0) sh[0] = x;
    }
    __syncthreads();
    return sh[0];
}

__device__ __forceinline__ float blockReduceMax(float v) {
    __shared__ float sh[8];
    __syncthreads();
    #pragma unroll
    for (int o = 16; o > 0; o >>= 1) v = fmaxf(v, __shfl_xor_sync(0xffffffffu, v, o));
    int lane = threadIdx.x & 31, w = threadIdx.x >> 5;
    if (lane == 0) sh[w] = v;
    __syncthreads();
    if (w == 0) {
        float x = (lane < 8) ? sh[lane] : -3.4e38f;
        #pragma unroll
        for (int o = 4; o > 0; o >>= 1) x = fmaxf(x, __shfl_xor_sync(0xffffffffu, x, o));
        if (lane == 0) sh[0] = x;
    }
    __syncthreads();
    return sh[0];
}

// ---------------- generic batched tf32 wmma GEMM, cp.async double-buffered ----------------
// C[z][M,N] = alpha * A[z][M,K] * B[z][K,N] (+ C_old if ACC)
// A row-major. B row-major if !BCOL, else B(k,n) = Bptr[n*ldb + k].
// Requires: M%128==0, N%128==0, K%32==0, 16B-aligned pointers & lds.

#define BM 128
#define BN 128
#define BK 32
#define APAD  36    // 144B row stride (multiple of 16B)
#define BNPAD 132   // 528B row stride (multiple of 16B)

template<bool BCOL, bool ACC>
__global__ __launch_bounds__(256, 2)
void gemm_tf32(const float* __restrict__ Abase, long long sA1, long long sA2, int lda,
               const float* __restrict__ Bbase, long long sB1, long long sB2, int ldb,
               float*       __restrict__ Cbase, long long sC1, long long sC2, int ldc,
               int K, int Z2, float alpha)
{
    extern __shared__ float smem[];
    constexpr int ASTG = BM * APAD;                        // floats per A stage
    constexpr int BSTG = BCOL ? (BM * APAD) : (BK * BNPAD);
    float* As = smem;               // 2 stages
    float* Bs = smem + 2 * ASTG;    // 2 stages

    const int z  = blockIdx.z;
    const int z1 = z / Z2, z2 = z % Z2;
    const float* A = Abase + (size_t)z1 * sA1 + (size_t)z2 * sA2;
    const float* B = Bbase + (size_t)z1 * sB1 + (size_t)z2 * sB2;
    float*       C = Cbase + (size_t)z1 * sC1 + (size_t)z2 * sC2;

    const int m0 = blockIdx.y * BM;
    const int n0 = blockIdx.x * BN;

    const int tid    = threadIdx.x;
    const int wid    = tid >> 5;
    const int warp_m = wid & 3;   // 4 warps along M (32 rows each)
    const int warp_n = wid >> 2;  // 2 warps along N (64 cols each)

    wmma::fragment<wmma::accumulator, 16, 16, 8, float> c[2][4];
    #pragma unroll
    for (int mi = 0; mi < 2; mi++)
        #pragma unroll
        for (int ni = 0; ni < 4; ni++)
            wmma::fill_fragment(c[mi][ni], 0.0f);

    // stage one BK-slab (it) into buffer buf
    auto stage = [&](int it, int buf) {
        const int k0 = it * BK;
        float* as = As + buf * ASTG;
        #pragma unroll
        for (int i = 0; i < 4; i++) {           // 1024 float4: 128 rows x 8
            int f4  = tid + i * 256;
            int row = f4 >> 3;
            int c4  = f4 & 7;
            cp16(as + row * APAD + c4 * 4,
                 A + (size_t)(m0 + row) * lda + k0 + c4 * 4);
        }
        float* bs = Bs + buf * BSTG;
        if (BCOL) {
            #pragma unroll
            for (int i = 0; i < 4; i++) {       // Bs[n][k]: 128 rows x 8
                int f4  = tid + i * 256;
                int row = f4 >> 3;
                int c4  = f4 & 7;
                cp16(bs + row * APAD + c4 * 4,
                     B + (size_t)(n0 + row) * ldb + k0 + c4 * 4);
            }
        } else {
            #pragma unroll
            for (int i = 0; i < 4; i++) {       // Bs[k][n]: 32 rows x 32
                int f4  = tid + i * 256;
                int row = f4 >> 5;
                int c4  = f4 & 31;
                cp16(bs + row * BNPAD + c4 * 4,
                     B + (size_t)(k0 + row) * ldb + n0 + c4 * 4);
            }
        }
    };

    const int T = K / BK;
    stage(0, 0);
    cp_commit();

    for (int it = 0; it < T; it++) {
        if (it + 1 < T) stage(it + 1, (it + 1) & 1);
        cp_commit();                  // unconditional: keeps group accounting aligned
        cp_wait1();                   // stage `it` fully landed
        __syncthreads();

        const float* as = As + (it & 1) * ASTG;
        const float* bs = Bs + (it & 1) * BSTG;

        #pragma unroll
        for (int kk = 0; kk < BK; kk += 8) {
            wmma::fragment<wmma::matrix_a, 16, 16, 8, wmma::precision::tf32, wmma::row_major> a[2];
            #pragma unroll
            for (int mi = 0; mi < 2; mi++) {
                wmma::load_matrix_sync(a[mi], as + (warp_m * 32 + mi * 16) * APAD + kk, APAD);
                #pragma unroll
                for (int t = 0; t < a[mi].num_elements; t++)
                    a[mi].x[t] = wmma::__float_to_tf32(a[mi].x[t]);
            }
            if (BCOL) {
                wmma::fragment<wmma::matrix_b, 16, 16, 8, wmma::precision::tf32, wmma::col_major> b[4];
                #pragma unroll
                for (int ni = 0; ni < 4; ni++) {
                    wmma::load_matrix_sync(b[ni], bs + (warp_n * 64 + ni * 16) * APAD + kk, APAD);
                    #pragma unroll
                    for (int t = 0; t < b[ni].num_elements; t++)
                        b[ni].x[t] = wmma::__float_to_tf32(b[ni].x[t]);
                }
                #pragma unroll
                for (int mi = 0; mi < 2; mi++)
                    #pragma unroll
                    for (int ni = 0; ni < 4; ni++)
                        wmma::mma_sync(c[mi][ni], a[mi], b[ni], c[mi][ni]);
            } else {
                wmma::fragment<wmma::matrix_b, 16, 16, 8, wmma::precision::tf32, wmma::row_major> b[4];
                #pragma unroll
                for (int ni = 0; ni < 4; ni++) {
                    wmma::load_matrix_sync(b[ni], bs + kk * BNPAD + warp_n * 64 + ni * 16, BNPAD);
                    #pragma unroll
                    for (int t = 0; t < b[ni].num_elements; t++)
                        b[ni].x[t] = wmma::__float_to_tf32(b[ni].x[t]);
                }
                #pragma unroll
                for (int mi = 0; mi < 2; mi++)
                    #pragma unroll
                    for (int ni = 0; ni < 4; ni++)
                        wmma::mma_sync(c[mi][ni], a[mi], b[ni], c[mi][ni]);
            }
        }
        __syncthreads();   // safe to overwrite this buffer next round
    }

    // --- epilogue ---
    #pragma unroll
    for (int mi = 0; mi < 2; mi++) {
        #pragma unroll
        for (int ni = 0; ni < 4; ni++) {
            float* Cp = C + (size_t)(m0 + warp_m * 32 + mi * 16) * ldc
                          + n0 + warp_n * 64 + ni * 16;
            #pragma unroll
            for (int t = 0; t < c[mi][ni].num_elements; t++)
                c[mi][ni].x[t] *= alpha;
            if (ACC) {
                wmma::fragment<wmma::accumulator, 16, 16, 8, float> old;
                wmma::load_matrix_sync(old, Cp, ldc, wmma::mem_row_major);
                #pragma unroll
                for (int t = 0; t < c[mi][ni].num_elements; t++)
                    c[mi][ni].x[t] += old.x[t];
            }
            wmma::store_matrix_sync(Cp, c[mi][ni], ldc, wmma::mem_row_major);
        }
    }
}

// smem bytes per instantiation
static inline int gemm_smem_bytes(bool bcol) {
    int astg = BM * APAD;
    int bstg = bcol ? (BM * APAD) : (BK * BNPAD);
    return (int)(2 * (astg + bstg) * sizeof(float));
}

// ---------------- mask dtype detection ----------------
__global__ void detect_mask_kernel(const unsigned* __restrict__ m) {
    __shared__ int votes[2];  // [0]=byte, [1]=float
    if (threadIdx.x < 2) votes[threadIdx.x] = 0;
    __syncthreads();
    for (int i = threadIdx.x; i < 2048; i += blockDim.x) {
        unsigned w = m[i];
        if (w > 1u) {
            if (w == 0x3F800000u) atomicOr(&votes[1], 1);
            else                  atomicOr(&votes[0], 1);
        }
    }
    __syncthreads();
    if (threadIdx.x == 0)
        g_mask_kind = votes[0] ? 1 : (votes[1] ? 2 : 0);
}

// ---------------- masked softmax + query-mask, in-place on attns (float4) ----------------
__global__ __launch_bounds__(256)
void softmax_kernel(float* __restrict__ attns,
                    const void* __restrict__ mask,
                    const float* __restrict__ qmask)
{
    const int r  = blockIdx.x;           // 0 .. 64*1024-1
    const int q  = r & (SQ - 1);
    const int hb = r >> 10;
    const int b  = hb & (BATCH - 1);
    float4* row4 = reinterpret_cast<float4*>(attns + (size_t)r * SK);
    const size_t m4 = (((size_t)b * SQ + q) * (size_t)SK) >> 2;
    const int t = threadIdx.x;
    const int kind = g_mask_kind;

    float4 v = row4[t];
    if (kind == 0) {
        int4 m = reinterpret_cast<const int4*>(mask)[m4 + t];
        if (m.x) v.x = NEGV;
        if (m.y) v.y = NEGV;
        if (m.z) v.z = NEGV;
        if (m.w) v.w = NEGV;
    } else if (kind == 1) {
        uchar4 m = reinterpret_cast<const uchar4*>(mask)[m4 + t];
        if (m.x) v.x = NEGV;
        if (m.y) v.y = NEGV;
        if (m.z) v.z = NEGV;
        if (m.w) v.w = NEGV;
    } else {
        float4 m = reinterpret_cast<const float4*>(mask)[m4 + t];
        if (m.x != 0.0f) v.x = NEGV;
        if (m.y != 0.0f) v.y = NEGV;
        if (m.z != 0.0f) v.z = NEGV;
        if (m.w != 0.0f) v.w = NEGV;
    }

    float mx = fmaxf(fmaxf(v.x, v.y), fmaxf(v.z, v.w));
    mx = blockReduceMax(mx);

    float4 p;
    p.x = __expf(v.x - mx);
    p.y = __expf(v.y - mx);
    p.z = __expf(v.z - mx);
    p.w = __expf(v.w - mx);
    float s = (p.x + p.y) + (p.z + p.w);
    s = blockReduceSum(s);

    const float scale = qmask[b * SQ + q] / s;
    p.x *= scale; p.y *= scale; p.z *= scale; p.w *= scale;
    row4[t] = p;
}

// ---------------- residual + bias + LayerNorm (float4) ----------------
__global__ __launch_bounds__(256)
void ln_kernel(const float* __restrict__ y, const float* __restrict__ dec,
               const float* __restrict__ bf, const float* __restrict__ gamma,
               const float* __restrict__ beta, float* __restrict__ out)
{
    const size_t base4 = ((size_t)blockIdx.x * D_) >> 2;
    const int t = threadIdx.x;
    const float4 y4 = reinterpret_cast<const float4*>(y)[base4 + t];
    const float4 d4 = reinterpret_cast<const float4*>(dec)[base4 + t];
    const float4 b4 = reinterpret_cast<const float4*>(bf)[t];
    float4 x;
    x.x = y4.x + b4.x + d4.x;
    x.y = y4.y + b4.y + d4.y;
    x.z = y4.z + b4.z + d4.z;
    x.w = y4.w + b4.w + d4.w;

    float s  = (x.x + x.y) + (x.z + x.w);
    float ss = (x.x * x.x + x.y * x.y) + (x.z * x.z + x.w * x.w);
    s  = blockReduceSum(s);
    ss = blockReduceSum(ss);
    const float mu   = s * (1.0f / D_);
    const float var  = ss * (1.0f / D_) - mu * mu;
    const float rstd = rsqrtf(var + 1e-5f);

    const float4 g4 = reinterpret_cast<const float4*>(gamma)[t];
    const float4 be4 = reinterpret_cast<const float4*>(beta)[t];
    float4 o;
    o.x = (x.x - mu) * rstd * g4.x + be4.x;
    o.y = (x.y - mu) * rstd * g4.y + be4.y;
    o.z = (x.z - mu) * rstd * g4.z + be4.z;
    o.w = (x.w - mu) * rstd * g4.w + be4.w;
    reinterpret_cast<float4*>(out)[base4 + t] = o;
}

// ---------------- launcher ----------------
extern "C" void kernel_launch(void* const* d_in, const int* in_sizes, int n_in,
                              void* d_out, int out_size)
{
    (void)in_sizes; (void)n_in; (void)out_size;
    const float* memory = (const float*)d_in[0];
    const float* dec    = (const float*)d_in[1];
    const float* qmask  = (const float*)d_in[2];
    const float* Wk     = (const float*)d_in[3];
    const float* Wv     = (const float*)d_in[4];
    const float* Wq     = (const float*)d_in[5];
    const float* Wf     = (const float*)d_in[6];
    const float* bf     = (const float*)d_in[7];
    const float* gamma  = (const float*)d_in[8];
    const float* beta   = (const float*)d_in[9];
    const void*  mask   = d_in[10];

    float* out_x = (float*)d_out;
    float* attns = out_x + (size_t)BATCH * SQ * D_;   // x first, then attns

    float *gK, *gV, *gQ, *gX, *gY;
    cudaGetSymbolAddress((void**)&gK, g_K);
    cudaGetSymbolAddress((void**)&gV, g_V);
    cudaGetSymbolAddress((void**)&gQ, g_Q);
    cudaGetSymbolAddress((void**)&gX, g_X);
    cudaGetSymbolAddress((void**)&gY, g_Y);

    const int smemR = gemm_smem_bytes(false);  // row-major B variant
    const int smemC = gemm_smem_bytes(true);   // col-major (BCOL) variant
    cudaFuncSetAttribute(gemm_tf32<false, false>,
                         cudaFuncAttributeMaxDynamicSharedMemorySize, smemR);
    cudaFuncSetAttribute(gemm_tf32<false, true>,
                         cudaFuncAttributeMaxDynamicSharedMemorySize, smemR);
    cudaFuncSetAttribute(gemm_tf32<true, false>,
                         cudaFuncAttributeMaxDynamicSharedMemorySize, smemC);

    const dim3 blk(256);
    const long long SqD  = (long long)SQ * D_;
    const long long SkD  = (long long)SK * D_;
    const long long SqSk = (long long)SQ * SK;
    const float inv_sqrt_dh = 0.08838834764831843f;  // 1/sqrt(128)

    // 1) projections: [8192,1024] x [1024,1024]
    gemm_tf32<false, false><<<dim3(D_ / BN, (BATCH * SK) / BM, 1), blk, smemR>>>(
        memory, 0, 0, D_, Wk, 0, 0, D_, gK, 0, 0, D_, D_, 1, 1.0f);
    gemm_tf32<false, false><<<dim3(D_ / BN, (BATCH * SK) / BM, 1), blk, smemR>>>(
        memory, 0, 0, D_, Wv, 0, 0, D_, gV, 0, 0, D_, D_, 1, 1.0f);
    gemm_tf32<false, false><<<dim3(D_ / BN, (BATCH * SQ) / BM, 1), blk, smemR>>>(
        dec, 0, 0, D_, Wq, 0, 0, D_, gQ, 0, 0, D_, D_, 1, 1.0f);

    // 2) scores: per (head,b): S = Q_hb @ K_hb^T / sqrt(dh) -> attns region (raw)
    gemm_tf32<true, false><<<dim3(SK / BN, SQ / BM, NH * BATCH), blk, smemC>>>(
        gQ, DH, SqD, D_,
        gK, DH, SkD, D_,
        attns, (long long)BATCH * SqSk, SqSk, SK,
        DH, BATCH, inv_sqrt_dh);

    // 3) mask dtype detect + masked softmax + query-mask (in-place in d_out)
    detect_mask_kernel<<<1, 256>>>((const unsigned*)mask);
    softmax_kernel<<<NH * BATCH * SQ, 256>>>(attns, mask, qmask);

    // 4) attn @ V: per (head,b): [1024,1024] x [1024,128] -> gX (heads concat)
    gemm_tf32<false, false><<<dim3(DH / BN, SQ / BM, NH * BATCH), blk, smemR>>>(
        attns, (long long)BATCH * SqSk, SqSk, SK,
        gV, DH, SkD, D_,
        gX, DH, SqD, D_,
        SK, BATCH, 1.0f);

    // 5) y = dec @ Wf[:D] ; y += x_attn @ Wf[D:]
    gemm_tf32<false, false><<<dim3(D_ / BN, (BATCH * SQ) / BM, 1), blk, smemR>>>(
        dec, 0, 0, D_, Wf, 0, 0, D_, gY, 0, 0, D_, D_, 1, 1.0f);
    gemm_tf32<false, true><<<dim3(D_ / BN, (BATCH * SQ) / BM, 1), blk, smemR>>>(
        gX, 0, 0, D_, Wf + (size_t)D_ * D_, 0, 0, D_, gY, 0, 0, D_, D_, 1, 1.0f);

    // 6) residual + bias + LayerNorm -> x output
    ln_kernel<<<BATCH * SQ, 256>>>(gY, dec, bf, gamma, beta, out_x);
}

// round 8
// speedup vs baseline: 1.3176x; 1.0177x over previous
#include <cuda_runtime.h>
#include <mma.h>
#include <cstdint>

using namespace nvcuda;

// Problem dims (fixed by the dataset)
#define D_    1024
#define SQ    1024
#define SK    1024
#define BATCH 8
#define NH    8
#define DH    128

#define NEGV  (-4294967295.0f)   // -2^32 + 1

// ---------------- scratch (device globals: no allocation allowed) ----------------
__device__ float g_K[(size_t)BATCH * SK * D_];   // round_tf32(memory @ Wk)
__device__ float g_V[(size_t)BATCH * SK * D_];   // round_tf32(memory @ Wv)
__device__ float g_Q[(size_t)BATCH * SQ * D_];   // round_tf32(dec @ Wq)
__device__ float g_X[(size_t)BATCH * SQ * D_];   // round_tf32(attn @ V)
__device__ float g_Y[(size_t)BATCH * SQ * D_];   // concat @ Wf (full fp32)
__device__ float g_MR[(size_t)BATCH * SK * D_];  // round_tf32(memory)
__device__ float g_DR[(size_t)BATCH * SQ * D_];  // round_tf32(decoder_input)
__device__ float g_W[(size_t)5 * 1024 * 1024];   // WkR | WvR | WqR | WfR(2M)
__device__ int   g_mask_kind;                    // 0=int32, 1=byte, 2=float32

// ---------------- helpers ----------------
__device__ __forceinline__ float tf32r(float v) {
    uint32_t o;
    asm("cvt.rna.tf32.f32 %0, %1;" : "=r"(o) : "f"(v));
    return __uint_as_float(o);
}
__device__ __forceinline__ void cp16(void* smem_dst, const void* gsrc) {
    uint32_t s = (uint32_t)__cvta_generic_to_shared(smem_dst);
    asm volatile("cp.async.cg.shared.global [%0], [%1], 16;\n" :: "r"(s), "l"(gsrc));
}
__device__ __forceinline__ void cp_commit() { asm volatile("cp.async.commit_group;\n"); }
__device__ __forceinline__ void cp_wait2()  { asm volatile("cp.async.wait_group 2;\n"); }

// ---------------- reductions ----------------
__device__ __forceinline__ float blockReduceSum(float v) {
    __shared__ float sh[8];
    __syncthreads();
    #pragma unroll
    for (int o = 16; o > 0; o >>= 1) v += __shfl_xor_sync(0xffffffffu, v, o);
    int lane = threadIdx.x & 31, w = threadIdx.x >> 5;
    if (lane == 0) sh[w] = v;
    __syncthreads();
    if (w == 0) {
        float x = (lane < 8) ? sh[lane] : 0.0f;
        #pragma unroll
        for (int o = 4; o > 0; o >>= 1) x += __shfl_xor_sync(0xffffffffu, x, o);
        if (lane == 0) sh[0] = x;
    }
    __syncthreads();
    return sh[0];
}
__device__ __forceinline__ float blockReduceMax(float v) {
    __shared__ float sh[8];
    __syncthreads();
    #pragma unroll
    for (int o = 16; o > 0; o >>= 1) v = fmaxf(v, __shfl_xor_sync(0xffffffffu, v, o));
    int lane = threadIdx.x & 31, w = threadIdx.x >> 5;
    if (lane == 0) sh[w] = v;
    __syncthreads();
    if (w == 0) {
        float x = (lane < 8) ? sh[lane] : -3.4e38f;
        #pragma unroll
        for (int o = 4; o > 0; o >>= 1) x = fmaxf(x, __shfl_xor_sync(0xffffffffu, x, o));
        if (lane == 0) sh[0] = x;
    }
    __syncthreads();
    return sh[0];
}

// ---------------- elementwise round-to-tf32 copy (float4) ----------------
__global__ __launch_bounds__(256)
void round_copy_kernel(const float4* __restrict__ in, float4* __restrict__ out, int n4)
{
    int i = blockIdx.x * 256 + threadIdx.x;
    if (i < n4) {
        float4 v = in[i];
        v.x = tf32r(v.x); v.y = tf32r(v.y); v.z = tf32r(v.z); v.w = tf32r(v.w);
        out[i] = v;
    }
}

// ---------------- generic batched tf32 wmma GEMM, 3-stage cp.async ----------------
// C[z][M,N] = alpha * A[z][M,K] * B[z][K,N] (+ C_old if ACC)
// A row-major. B row-major if !BCOL, else B(k,n) = Bptr[n*ldb + k].
// ALL operands must already be tf32-rounded (low 13 mantissa bits zero) -> no cvt
// needed in the MMA loop; HMMA truncation is exact.
// ROUND: round outputs to tf32 (for intermediates feeding later GEMMs).
// Requires: M%128==0, N%128==0, K%32==0, K/32 >= 3, 16B-aligned pointers & lds.

#define BM 128
#define BN 128
#define BK 32
#define APAD  36    // 144B row stride (multiple of 16B)
#define BNPAD 132   // 528B row stride (multiple of 16B)
#define NST 3

template<bool BCOL, bool ACC, bool ROUND>
__global__ __launch_bounds__(256, 2)
void gemm_tf32(const float* __restrict__ Abase, long long sA1, long long sA2, int lda,
               const float* __restrict__ Bbase, long long sB1, long long sB2, int ldb,
               float*       __restrict__ Cbase, long long sC1, long long sC2, int ldc,
               int K, int Z2, float alpha)
{
    extern __shared__ float smem[];
    constexpr int ASTG = BM * APAD;
    constexpr int BSTG = BCOL ? (BM * APAD) : (BK * BNPAD);
    float* As = smem;                 // NST stages
    float* Bs = smem + NST * ASTG;    // NST stages

    const int z  = blockIdx.z;
    const int z1 = z / Z2, z2 = z % Z2;
    const float* A = Abase + (size_t)z1 * sA1 + (size_t)z2 * sA2;
    const float* B = Bbase + (size_t)z1 * sB1 + (size_t)z2 * sB2;
    float*       C = Cbase + (size_t)z1 * sC1 + (size_t)z2 * sC2;

    const int m0 = blockIdx.y * BM;
    const int n0 = blockIdx.x * BN;

    const int tid    = threadIdx.x;
    const int wid    = tid >> 5;
    const int warp_m = wid & 3;   // 4 warps along M (32 rows each)
    const int warp_n = wid >> 2;  // 2 warps along N (64 cols each)

    wmma::fragment<wmma::accumulator, 16, 16, 8, float> c[2][4];
    #pragma unroll
    for (int mi = 0; mi < 2; mi++)
        #pragma unroll
        for (int ni = 0; ni < 4; ni++)
            wmma::fill_fragment(c[mi][ni], 0.0f);

    auto stage = [&](int it) {
        const int buf = it % NST;
        const int k0  = it * BK;
        float* as = As + buf * ASTG;
        #pragma unroll
        for (int i = 0; i < 4; i++) {           // 1024 float4: 128 rows x 8
            int f4  = tid + i * 256;
            int row = f4 >> 3;
            int c4  = f4 & 7;
            cp16(as + row * APAD + c4 * 4,
                 A + (size_t)(m0 + row) * lda + k0 + c4 * 4);
        }
        float* bs = Bs + buf * BSTG;
        if (BCOL) {
            #pragma unroll
            for (int i = 0; i < 4; i++) {       // Bs[n][k]: 128 rows x 8
                int f4  = tid + i * 256;
                int row = f4 >> 3;
                int c4  = f4 & 7;
                cp16(bs + row * APAD + c4 * 4,
                     B + (size_t)(n0 + row) * ldb + k0 + c4 * 4);
            }
        } else {
            #pragma unroll
            for (int i = 0; i < 4; i++) {       // Bs[k][n]: 32 rows x 32
                int f4  = tid + i * 256;
                int row = f4 >> 5;
                int c4  = f4 & 31;
                cp16(bs + row * BNPAD + c4 * 4,
                     B + (size_t)(k0 + row) * ldb + n0 + c4 * 4);
            }
        }
    };

    const int T = K / BK;       // >= 3 for all our GEMMs (min K = 128)
    stage(0); cp_commit();
    stage(1); cp_commit();

    for (int it = 0; it < T; it++) {
        if (it + 2 < T) stage(it + 2);
        cp_commit();                 // unconditional: keeps group accounting aligned
        cp_wait2();                  // slab `it` fully landed
        __syncthreads();

        const float* as = As + (it % NST) * ASTG;
        const float* bs = Bs + (it % NST) * BSTG;

        #pragma unroll
        for (int kk = 0; kk < BK; kk += 8) {
            wmma::fragment<wmma::matrix_a, 16, 16, 8, wmma::precision::tf32, wmma::row_major> a[2];
            #pragma unroll
            for (int mi = 0; mi < 2; mi++)
                wmma::load_matrix_sync(a[mi], as + (warp_m * 32 + mi * 16) * APAD + kk, APAD);
            if (BCOL) {
                wmma::fragment<wmma::matrix_b, 16, 16, 8, wmma::precision::tf32, wmma::col_major> b[4];
                #pragma unroll
                for (int ni = 0; ni < 4; ni++)
                    wmma::load_matrix_sync(b[ni], bs + (warp_n * 64 + ni * 16) * APAD + kk, APAD);
                #pragma unroll
                for (int mi = 0; mi < 2; mi++)
                    #pragma unroll
                    for (int ni = 0; ni < 4; ni++)
                        wmma::mma_sync(c[mi][ni], a[mi], b[ni], c[mi][ni]);
            } else {
                wmma::fragment<wmma::matrix_b, 16, 16, 8, wmma::precision::tf32, wmma::row_major> b[4];
                #pragma unroll
                for (int ni = 0; ni < 4; ni++)
                    wmma::load_matrix_sync(b[ni], bs + kk * BNPAD + warp_n * 64 + ni * 16, BNPAD);
                #pragma unroll
                for (int mi = 0; mi < 2; mi++)
                    #pragma unroll
                    for (int ni = 0; ni < 4; ni++)
                        wmma::mma_sync(c[mi][ni], a[mi], b[ni], c[mi][ni]);
            }
        }
        __syncthreads();
    }

    // --- epilogue ---
    #pragma unroll
    for (int mi = 0; mi < 2; mi++) {
        #pragma unroll
        for (int ni = 0; ni < 4; ni++) {
            float* Cp = C + (size_t)(m0 + warp_m * 32 + mi * 16) * ldc
                          + n0 + warp_n * 64 + ni * 16;
            #pragma unroll
            for (int t = 0; t < c[mi][ni].num_elements; t++)
                c[mi][ni].x[t] *= alpha;
            if (ACC) {
                wmma::fragment<wmma::accumulator, 16, 16, 8, float> old;
                wmma::load_matrix_sync(old, Cp, ldc, wmma::mem_row_major);
                #pragma unroll
                for (int t = 0; t < c[mi][ni].num_elements; t++)
                    c[mi][ni].x[t] += old.x[t];
            }
            if (ROUND) {
                #pragma unroll
                for (int t = 0; t < c[mi][ni].num_elements; t++)
                    c[mi][ni].x[t] = tf32r(c[mi][ni].x[t]);
            }
            wmma::store_matrix_sync(Cp, c[mi][ni], ldc, wmma::mem_row_major);
        }
    }
}

static inline int gemm_smem_bytes(bool bcol) {
    int astg = BM * APAD;
    int bstg = bcol ? (BM * APAD) : (BK * BNPAD);
    return (int)(NST * (astg + bstg) * sizeof(float));
}

// ---------------- mask dtype detection ----------------
__global__ void detect_mask_kernel(const unsigned* __restrict__ m) {
    __shared__ int votes[2];  // [0]=byte, [1]=float
    if (threadIdx.x < 2) votes[threadIdx.x] = 0;
    __syncthreads();
    for (int i = threadIdx.x; i < 2048; i += blockDim.x) {
        unsigned w = m[i];
        if (w > 1u) {
            if (w == 0x3F800000u) atomicOr(&votes[1], 1);
            else                  atomicOr(&votes[0], 1);
        }
    }
    __syncthreads();
    if (threadIdx.x == 0)
        g_mask_kind = votes[0] ? 1 : (votes[1] ? 2 : 0);
}

// ---------------- masked softmax + query-mask, in-place on attns (float4) ----------------
// Output is rounded to tf32: it both IS the attns output (tolerance 1e-3 >> 5e-4)
// and feeds the attn@V GEMM (which requires tf32-rounded operands).
__global__ __launch_bounds__(256)
void softmax_kernel(float* __restrict__ attns,
                    const void* __restrict__ mask,
                    const float* __restrict__ qmask)
{
    const int r  = blockIdx.x;           // 0 .. 64*1024-1
    const int q  = r & (SQ - 1);
    const int hb = r >> 10;
    const int b  = hb & (BATCH - 1);
    float4* row4 = reinterpret_cast<float4*>(attns + (size_t)r * SK);
    const size_t m4 = (((size_t)b * SQ + q) * (size_t)SK) >> 2;
    const int t = threadIdx.x;
    const int kind = g_mask_kind;

    float4 v = row4[t];
    if (kind == 0) {
        int4 m = reinterpret_cast<const int4*>(mask)[m4 + t];
        if (m.x) v.x = NEGV;
        if (m.y) v.y = NEGV;
        if (m.z) v.z = NEGV;
        if (m.w) v.w = NEGV;
    } else if (kind == 1) {
        uchar4 m = reinterpret_cast<const uchar4*>(mask)[m4 + t];
        if (m.x) v.x = NEGV;
        if (m.y) v.y = NEGV;
        if (m.z) v.z = NEGV;
        if (m.w) v.w = NEGV;
    } else {
        float4 m = reinterpret_cast<const float4*>(mask)[m4 + t];
        if (m.x != 0.0f) v.x = NEGV;
        if (m.y != 0.0f) v.y = NEGV;
        if (m.z != 0.0f) v.z = NEGV;
        if (m.w != 0.0f) v.w = NEGV;
    }

    float mx = fmaxf(fmaxf(v.x, v.y), fmaxf(v.z, v.w));
    mx = blockReduceMax(mx);

    float4 p;
    p.x = __expf(v.x - mx);
    p.y = __expf(v.y - mx);
    p.z = __expf(v.z - mx);
    p.w = __expf(v.w - mx);
    float s = (p.x + p.y) + (p.z + p.w);
    s = blockReduceSum(s);

    const float scale = qmask[b * SQ + q] / s;
    p.x = tf32r(p.x * scale);
    p.y = tf32r(p.y * scale);
    p.z = tf32r(p.z * scale);
    p.w = tf32r(p.w * scale);
    row4[t] = p;
}

// ---------------- residual + bias + LayerNorm (float4) ----------------
__global__ __launch_bounds__(256)
void ln_kernel(const float* __restrict__ y, const float* __restrict__ dec,
               const float* __restrict__ bf, const float* __restrict__ gamma,
               const float* __restrict__ beta, float* __restrict__ out)
{
    const size_t base4 = ((size_t)blockIdx.x * D_) >> 2;
    const int t = threadIdx.x;
    const float4 y4 = reinterpret_cast<const float4*>(y)[base4 + t];
    const float4 d4 = reinterpret_cast<const float4*>(dec)[base4 + t];
    const float4 b4 = reinterpret_cast<const float4*>(bf)[t];
    float4 x;
    x.x = y4.x + b4.x + d4.x;
    x.y = y4.y + b4.y + d4.y;
    x.z = y4.z + b4.z + d4.z;
    x.w = y4.w + b4.w + d4.w;

    float s  = (x.x + x.y) + (x.z + x.w);
    float ss = (x.x * x.x + x.y * x.y) + (x.z * x.z + x.w * x.w);
    s  = blockReduceSum(s);
    ss = blockReduceSum(ss);
    const float mu   = s * (1.0f / D_);
    const float var  = ss * (1.0f / D_) - mu * mu;
    const float rstd = rsqrtf(var + 1e-5f);

    const float4 g4  = reinterpret_cast<const float4*>(gamma)[t];
    const float4 be4 = reinterpret_cast<const float4*>(beta)[t];
    float4 o;
    o.x = (x.x - mu) * rstd * g4.x + be4.x;
    o.y = (x.y - mu) * rstd * g4.y + be4.y;
    o.z = (x.z - mu) * rstd * g4.z + be4.z;
    o.w = (x.w - mu) * rstd * g4.w + be4.w;
    reinterpret_cast<float4*>(out)[base4 + t] = o;
}

// ---------------- launcher ----------------
extern "C" void kernel_launch(void* const* d_in, const int* in_sizes, int n_in,
                              void* d_out, int out_size)
{
    (void)in_sizes; (void)n_in; (void)out_size;
    const float* memory = (const float*)d_in[0];
    const float* dec    = (const float*)d_in[1];
    const float* qmask  = (const float*)d_in[2];
    const float* Wk     = (const float*)d_in[3];
    const float* Wv     = (const float*)d_in[4];
    const float* Wq     = (const float*)d_in[5];
    const float* Wf     = (const float*)d_in[6];
    const float* bf     = (const float*)d_in[7];
    const float* gamma  = (const float*)d_in[8];
    const float* beta   = (const float*)d_in[9];
    const void*  mask   = d_in[10];

    float* out_x = (float*)d_out;
    float* attns = out_x + (size_t)BATCH * SQ * D_;   // x first, then attns

    float *gK, *gV, *gQ, *gX, *gY, *gMR, *gDR, *gW;
    cudaGetSymbolAddress((void**)&gK,  g_K);
    cudaGetSymbolAddress((void**)&gV,  g_V);
    cudaGetSymbolAddress((void**)&gQ,  g_Q);
    cudaGetSymbolAddress((void**)&gX,  g_X);
    cudaGetSymbolAddress((void**)&gY,  g_Y);
    cudaGetSymbolAddress((void**)&gMR, g_MR);
    cudaGetSymbolAddress((void**)&gDR, g_DR);
    cudaGetSymbolAddress((void**)&gW,  g_W);
    float* WkR = gW;
    float* WvR = gW + (size_t)1024 * 1024;
    float* WqR = gW + (size_t)2 * 1024 * 1024;
    float* WfR = gW + (size_t)3 * 1024 * 1024;   // 2M floats

    const int smemR = gemm_smem_bytes(false);
    const int smemC = gemm_smem_bytes(true);
    cudaFuncSetAttribute(gemm_tf32<false, false, true>,
                         cudaFuncAttributeMaxDynamicSharedMemorySize, smemR);
    cudaFuncSetAttribute(gemm_tf32<false, false, false>,
                         cudaFuncAttributeMaxDynamicSharedMemorySize, smemR);
    cudaFuncSetAttribute(gemm_tf32<false, true, false>,
                         cudaFuncAttributeMaxDynamicSharedMemorySize, smemR);
    cudaFuncSetAttribute(gemm_tf32<true, false, false>,
                         cudaFuncAttributeMaxDynamicSharedMemorySize, smemC);

    const dim3 blk(256);
    const long long SqD  = (long long)SQ * D_;
    const long long SkD  = (long long)SK * D_;
    const long long SqSk = (long long)SQ * SK;
    const float inv_sqrt_dh = 0.08838834764831843f;  // 1/sqrt(128)
    const int n4_act = (BATCH * SK * D_) / 4;        // 2,097,152
    const int n4_w1  = (D_ * D_) / 4;                // 262,144
    const int n4_wf  = (2 * D_ * D_) / 4;            // 524,288

    // 0) tf32-round all GEMM inputs once (removes all in-loop cvt)
    round_copy_kernel<<<(n4_act + 255) / 256, blk>>>((const float4*)memory, (float4*)gMR, n4_act);
    round_copy_kernel<<<(n4_act + 255) / 256, blk>>>((const float4*)dec,    (float4*)gDR, n4_act);
    round_copy_kernel<<<(n4_w1 + 255) / 256, blk>>>((const float4*)Wk, (float4*)WkR, n4_w1);
    round_copy_kernel<<<(n4_w1 + 255) / 256, blk>>>((const float4*)Wv, (float4*)WvR, n4_w1);
    round_copy_kernel<<<(n4_w1 + 255) / 256, blk>>>((const float4*)Wq, (float4*)WqR, n4_w1);
    round_copy_kernel<<<(n4_wf + 255) / 256, blk>>>((const float4*)Wf, (float4*)WfR, n4_wf);
    detect_mask_kernel<<<1, 256>>>((const unsigned*)mask);

    // 1) projections: [8192,1024] x [1024,1024] (outputs tf32-rounded)
    gemm_tf32<false, false, true><<<dim3(D_ / BN, (BATCH * SK) / BM, 1), blk, smemR>>>(
        gMR, 0, 0, D_, WkR, 0, 0, D_, gK, 0, 0, D_, D_, 1, 1.0f);
    gemm_tf32<false, false, true><<<dim3(D_ / BN, (BATCH * SK) / BM, 1), blk, smemR>>>(
        gMR, 0, 0, D_, WvR, 0, 0, D_, gV, 0, 0, D_, D_, 1, 1.0f);
    gemm_tf32<false, false, true><<<dim3(D_ / BN, (BATCH * SQ) / BM, 1), blk, smemR>>>(
        gDR, 0, 0, D_, WqR, 0, 0, D_, gQ, 0, 0, D_, D_, 1, 1.0f);

    // 2) scores: per (head,b): S = Q_hb @ K_hb^T / sqrt(dh) -> attns region (raw fp32)
    gemm_tf32<true, false, false><<<dim3(SK / BN, SQ / BM, NH * BATCH), blk, smemC>>>(
        gQ, DH, SqD, D_,
        gK, DH, SkD, D_,
        attns, (long long)BATCH * SqSk, SqSk, SK,
        DH, BATCH, inv_sqrt_dh);

    // 3) masked softmax + query-mask (in-place, output tf32-rounded)
    softmax_kernel<<<NH * BATCH * SQ, 256>>>(attns, mask, qmask);

    // 4) attn @ V: per (head,b): [1024,1024] x [1024,128] -> gX (rounded)
    gemm_tf32<false, false, true><<<dim3(DH / BN, SQ / BM, NH * BATCH), blk, smemR>>>(
        attns, (long long)BATCH * SqSk, SqSk, SK,
        gV, DH, SkD, D_,
        gX, DH, SqD, D_,
        SK, BATCH, 1.0f);

    // 5) y = dec @ Wf[:D] ; y += x_attn @ Wf[D:]   (full fp32 result)
    gemm_tf32<false, false, false><<<dim3(D_ / BN, (BATCH * SQ) / BM, 1), blk, smemR>>>(
        gDR, 0, 0, D_, WfR, 0, 0, D_, gY, 0, 0, D_, D_, 1, 1.0f);
    gemm_tf32<false, true, false><<<dim3(D_ / BN, (BATCH * SQ) / BM, 1), blk, smemR>>>(
        gX, 0, 0, D_, WfR + (size_t)D_ * D_, 0, 0, D_, gY, 0, 0, D_, D_, 1, 1.0f);

    // 6) residual + bias + LayerNorm -> x output (exact dec for residual)
    ln_kernel<<<BATCH * SQ, 256>>>(gY, dec, bf, gamma, beta, out_x);
}

// round 11
// speedup vs baseline: 4.0545x; 3.0773x over previous
#include <cuda_runtime.h>
#include <cuda_fp16.h>
#include <mma.h>
#include <cstdint>
#include <type_traits>

using namespace nvcuda;

// Problem dims (fixed by the dataset)
#define D_    1024
#define SQ    1024
#define SK    1024
#define BATCH 8
#define NH    8
#define DH    128

#define NEGV  (-4294967295.0f)   // -2^32 + 1

// ---------------- scratch (device globals: no allocation allowed) ----------------
__device__ __half g_memH[(size_t)BATCH * SK * D_];        // fp16(memory)            [8192,1024]
__device__ __half g_cat[(size_t)BATCH * SQ * 2 * D_];     // [fp16(dec) | attn@V]    [8192,2048]
__device__ __half g_Kh[(size_t)BATCH * SK * D_];          // fp16(memory @ Wk)
__device__ __half g_Vh[(size_t)BATCH * SK * D_];          // fp16(memory @ Wv)
__device__ __half g_Qh[(size_t)BATCH * SQ * D_];          // fp16(dec @ Wq)
__device__ __half g_Ph[(size_t)NH * BATCH * SQ * SK];     // fp16(softmax(attn))     128MB
__device__ __half g_Wh[(size_t)5 * 1024 * 1024];          // Wk|Wv|Wq|Wf(2M) fp16
__device__ float  g_Y[(size_t)BATCH * SQ * D_];           // concat @ Wf (fp32)
__device__ int    g_mask_kind;                            // 0=int32, 1=byte, 2=float32

// ---------------- helpers ----------------
__device__ __forceinline__ void cp16(void* smem_dst, const void* gsrc) {
    uint32_t s = (uint32_t)__cvta_generic_to_shared(smem_dst);
    asm volatile("cp.async.cg.shared.global [%0], [%1], 16;\n" :: "r"(s), "l"(gsrc));
}
__device__ __forceinline__ void cp_commit() { asm volatile("cp.async.commit_group;\n"); }
__device__ __forceinline__ void cp_wait2()  { asm volatile("cp.async.wait_group 2;\n"); }

// ---------------- reductions ----------------
__device__ __forceinline__ float blockReduceSum(float v) {
    __shared__ float sh[8];
    __syncthreads();
    #pragma unroll
    for (int o = 16; o > 0; o >>= 1) v += __shfl_xor_sync(0xffffffffu, v, o);
    int lane = threadIdx.x & 31, w = threadIdx.x >> 5;
    if (lane == 0) sh[w] = v;
    __syncthreads();
    if (w == 0) {
        float x = (lane < 8) ? sh[lane] : 0.0f;
        #pragma unroll
        for (int o = 4; o > 0; o >>= 1) x += __shfl_xor_sync(0xffffffffu, x, o);
        if (lane == 0) sh[0] = x;
    }
    __syncthreads();
    return sh[0];
}
__device__ __forceinline__ float blockReduceMax(float v) {
    __shared__ float sh[8];
    __syncthreads();
    #pragma unroll
    for (int o = 16; o > 0; o >>= 1) v = fmaxf(v, __shfl_xor_sync(0xffffffffu, v, o));
    int lane = threadIdx.x & 31, w = threadIdx.x >> 5;
    if (lane == 0) sh[w] = v;
    __syncthreads();
    if (w == 0) {
        float x = (lane < 8) ? sh[lane] : -3.4e38f;
        #pragma unroll
        for (int o = 4; o > 0; o >>= 1) x = fmaxf(x, __shfl_xor_sync(0xffffffffu, x, o));
        if (lane == 0) sh[0] = x;
    }
    __syncthreads();
    return sh[0];
}

// ---------------- fp32 -> fp16 conversion (8 elems/thread, 16B stores) ----------------
__global__ __launch_bounds__(256)
void f2h_kernel(const float4* __restrict__ in, uint4* __restrict__ out, int n8)
{
    int i = blockIdx.x * 256 + threadIdx.x;
    if (i < n8) {
        float4 a = in[2 * i], b = in[2 * i + 1];
        __half2 h0 = __floats2half2_rn(a.x, a.y);
        __half2 h1 = __floats2half2_rn(a.z, a.w);
        __half2 h2 = __floats2half2_rn(b.x, b.y);
        __half2 h3 = __floats2half2_rn(b.z, b.w);
        uint4 u;
        u.x = *reinterpret_cast<unsigned*>(&h0);
        u.y = *reinterpret_cast<unsigned*>(&h1);
        u.z = *reinterpret_cast<unsigned*>(&h2);
        u.w = *reinterpret_cast<unsigned*>(&h3);
        out[i] = u;
    }
}

// dec fp32 [8192,1024] -> fp16 into left half of cat [8192,2048]
__global__ __launch_bounds__(256)
void dec2cat_kernel(const float4* __restrict__ dec, __half* __restrict__ cat)
{
    int i = blockIdx.x * 256 + threadIdx.x;     // 1M threads, 8 elems each
    int row = i >> 7, c8 = i & 127;
    float4 a = dec[2 * i], b = dec[2 * i + 1];
    __half2 h0 = __floats2half2_rn(a.x, a.y);
    __half2 h1 = __floats2half2_rn(a.z, a.w);
    __half2 h2 = __floats2half2_rn(b.x, b.y);
    __half2 h3 = __floats2half2_rn(b.z, b.w);
    uint4 u;
    u.x = *reinterpret_cast<unsigned*>(&h0);
    u.y = *reinterpret_cast<unsigned*>(&h1);
    u.z = *reinterpret_cast<unsigned*>(&h2);
    u.w = *reinterpret_cast<unsigned*>(&h3);
    *reinterpret_cast<uint4*>(cat + (size_t)row * 2048 + c8 * 8) = u;
}

// ---------------- generic batched fp16 wmma GEMM, 3-stage cp.async ----------------
// C[z][M,N] = alpha * A[z][M,K] * B[z][K,N], fp32 accumulate.
// A row-major fp16. B row-major fp16 if !BCOL, else B(k,n)=Bptr[n*ldb+k].
// OutT = float (direct store) or __half (round epilogue).
// Requires: M%128==0, N%128==0, K%32==0, K/32 >= 3, 16B-aligned pointers & lds.

#define BM 128
#define BN 128
#define BK 32
#define APADh  40    // halfs: 80B row stride (16B multiple)
#define BNPADh 136   // halfs: 272B row stride (16B multiple)
#define NST 3

template<bool BCOL, typename OutT>
__global__ __launch_bounds__(256, 2)
void gemm_h(const __half* __restrict__ Abase, long long sA1, long long sA2, int lda,
            const __half* __restrict__ Bbase, long long sB1, long long sB2, int ldb,
            OutT*         __restrict__ Cbase, long long sC1, long long sC2, int ldc,
            int K, int Z2, float alpha)
{
    extern __shared__ __align__(16) __half smh[];
    constexpr int ASTG = BM * APADh;                        // 5120 halfs
    constexpr int BSTG = BCOL ? (BM * APADh) : (BK * BNPADh);
    __half* As = smh;
    __half* Bs = smh + NST * ASTG;

    const int z  = blockIdx.z;
    const int z1 = z / Z2, z2 = z % Z2;
    const __half* A = Abase + (size_t)z1 * sA1 + (size_t)z2 * sA2;
    const __half* B = Bbase + (size_t)z1 * sB1 + (size_t)z2 * sB2;
    OutT*         C = Cbase + (size_t)z1 * sC1 + (size_t)z2 * sC2;

    const int m0 = blockIdx.y * BM;
    const int n0 = blockIdx.x * BN;

    const int tid    = threadIdx.x;
    const int wid    = tid >> 5;
    const int warp_m = wid & 3;   // 4 warps along M (32 rows each)
    const int warp_n = wid >> 2;  // 2 warps along N (64 cols each)

    wmma::fragment<wmma::accumulator, 16, 16, 16, float> c[2][4];
    #pragma unroll
    for (int mi = 0; mi < 2; mi++)
        #pragma unroll
        for (int ni = 0; ni < 4; ni++)
            wmma::fill_fragment(c[mi][ni], 0.0f);

    auto stage = [&](int it) {
        const int buf = it % NST;
        const int k0  = it * BK;
        __half* as = As + buf * ASTG;
        #pragma unroll
        for (int i = 0; i < 2; i++) {           // A: 512 chunks (128 rows x 4x16B)
            int ch  = tid + i * 256;
            int row = ch >> 2;
            int c8  = ch & 3;
            cp16(as + row * APADh + c8 * 8,
                 A + (size_t)(m0 + row) * lda + k0 + c8 * 8);
        }
        __half* bs = Bs + buf * BSTG;
        if (BCOL) {
            #pragma unroll
            for (int i = 0; i < 2; i++) {       // Bs[n][k]: 128 rows x 4x16B
                int ch  = tid + i * 256;
                int row = ch >> 2;
                int c8  = ch & 3;
                cp16(bs + row * APADh + c8 * 8,
                     B + (size_t)(n0 + row) * ldb + k0 + c8 * 8);
            }
        } else {
            #pragma unroll
            for (int i = 0; i < 2; i++) {       // Bs[k][n]: 32 rows x 16x16B
                int ch  = tid + i * 256;
                int row = ch >> 4;
                int c8  = ch & 15;
                cp16(bs + row * BNPADh + c8 * 8,
                     B + (size_t)(k0 + row) * ldb + n0 + c8 * 8);
            }
        }
    };

    const int T = K / BK;       // >= 3 for all our GEMMs (min K = 128)
    stage(0); cp_commit();
    stage(1); cp_commit();

    for (int it = 0; it < T; it++) {
        if (it + 2 < T) stage(it + 2);
        cp_commit();                 // unconditional: keeps group accounting aligned
        cp_wait2();                  // slab `it` fully landed
        __syncthreads();

        const __half* as = As + (it % NST) * ASTG;
        const __half* bs = Bs + (it % NST) * BSTG;

        #pragma unroll
        for (int kk = 0; kk < BK; kk += 16) {
            wmma::fragment<wmma::matrix_a, 16, 16, 16, __half, wmma::row_major> a[2];
            #pragma unroll
            for (int mi = 0; mi < 2; mi++)
                wmma::load_matrix_sync(a[mi], as + (warp_m * 32 + mi * 16) * APADh + kk, APADh);
            if (BCOL) {
                wmma::fragment<wmma::matrix_b, 16, 16, 16, __half, wmma::col_major> b[4];
                #pragma unroll
                for (int ni = 0; ni < 4; ni++)
                    wmma::load_matrix_sync(b[ni], bs + (warp_n * 64 + ni * 16) * APADh + kk, APADh);
                #pragma unroll
                for (int mi = 0; mi < 2; mi++)
                    #pragma unroll
                    for (int ni = 0; ni < 4; ni++)
                        wmma::mma_sync(c[mi][ni], a[mi], b[ni], c[mi][ni]);
            } else {
                wmma::fragment<wmma::matrix_b, 16, 16, 16, __half, wmma::row_major> b[4];
                #pragma unroll
                for (int ni = 0; ni < 4; ni++)
                    wmma::load_matrix_sync(b[ni], bs + kk * BNPADh + warp_n * 64 + ni * 16, BNPADh);
                #pragma unroll
                for (int mi = 0; mi < 2; mi++)
                    #pragma unroll
                    for (int ni = 0; ni < 4; ni++)
                        wmma::mma_sync(c[mi][ni], a[mi], b[ni], c[mi][ni]);
            }
        }
        __syncthreads();
    }

    // --- epilogue ---
    #pragma unroll
    for (int mi = 0; mi < 2; mi++) {
        #pragma unroll
        for (int ni = 0; ni < 4; ni++) {
            OutT* Cp = C + (size_t)(m0 + warp_m * 32 + mi * 16) * ldc
                         + n0 + warp_n * 64 + ni * 16;
            if constexpr (std::is_same<OutT, float>::value) {
                #pragma unroll
                for (int t = 0; t < c[mi][ni].num_elements; t++)
                    c[mi][ni].x[t] *= alpha;
                wmma::store_matrix_sync(Cp, c[mi][ni], ldc, wmma::mem_row_major);
            } else {
                wmma::fragment<wmma::accumulator, 16, 16, 16, __half> hc;
                #pragma unroll
                for (int t = 0; t < hc.num_elements; t++)
                    hc.x[t] = __float2half(c[mi][ni].x[t] * alpha);
                wmma::store_matrix_sync(Cp, hc, ldc, wmma::mem_row_major);
            }
        }
    }
}

static inline int gemm_smem_bytes(bool bcol) {
    int astg = BM * APADh;
    int bstg = bcol ? (BM * APADh) : (BK * BNPADh);
    return (int)(NST * (astg + bstg) * sizeof(__half));
}

// ---------------- mask dtype detection ----------------
__global__ void detect_mask_kernel(const unsigned* __restrict__ m) {
    __shared__ int votes[2];  // [0]=byte, [1]=float
    if (threadIdx.x < 2) votes[threadIdx.x] = 0;
    __syncthreads();
    for (int i = threadIdx.x; i < 2048; i += blockDim.x) {
        unsigned w = m[i];
        if (w > 1u) {
            if (w == 0x3F800000u) atomicOr(&votes[1], 1);
            else                  atomicOr(&votes[0], 1);
        }
    }
    __syncthreads();
    if (threadIdx.x == 0)
        g_mask_kind = votes[0] ? 1 : (votes[1] ? 2 : 0);
}

// ---------------- masked softmax + query-mask ----------------
// Reads raw fp32 scores from attns, writes fp32 attns (output) + fp16 copy for GEMM.
__global__ __launch_bounds__(256)
void softmax_kernel(float* __restrict__ attns, __half* __restrict__ ph,
                    const void* __restrict__ mask,
                    const float* __restrict__ qmask)
{
    const int r  = blockIdx.x;           // 0 .. 64*1024-1
    const int q  = r & (SQ - 1);
    const int hb = r >> 10;
    const int b  = hb & (BATCH - 1);
    float4* row4 = reinterpret_cast<float4*>(attns + (size_t)r * SK);
    const size_t m4 = (((size_t)b * SQ + q) * (size_t)SK) >> 2;
    const int t = threadIdx.x;
    const int kind = g_mask_kind;

    float4 v = row4[t];
    if (kind == 0) {
        int4 m = reinterpret_cast<const int4*>(mask)[m4 + t];
        if (m.x) v.x = NEGV;
        if (m.y) v.y = NEGV;
        if (m.z) v.z = NEGV;
        if (m.w) v.w = NEGV;
    } else if (kind == 1) {
        uchar4 m = reinterpret_cast<const uchar4*>(mask)[m4 + t];
        if (m.x) v.x = NEGV;
        if (m.y) v.y = NEGV;
        if (m.z) v.z = NEGV;
        if (m.w) v.w = NEGV;
    } else {
        float4 m = reinterpret_cast<const float4*>(mask)[m4 + t];
        if (m.x != 0.0f) v.x = NEGV;
        if (m.y != 0.0f) v.y = NEGV;
        if (m.z != 0.0f) v.z = NEGV;
        if (m.w != 0.0f) v.w = NEGV;
    }

    float mx = fmaxf(fmaxf(v.x, v.y), fmaxf(v.z, v.w));
    mx = blockReduceMax(mx);

    float4 p;
    p.x = __expf(v.x - mx);
    p.y = __expf(v.y - mx);
    p.z = __expf(v.z - mx);
    p.w = __expf(v.w - mx);
    float s = (p.x + p.y) + (p.z + p.w);
    s = blockReduceSum(s);

    const float scale = qmask[b * SQ + q] / s;
    p.x *= scale; p.y *= scale; p.z *= scale; p.w *= scale;
    row4[t] = p;

    __half2 h0 = __floats2half2_rn(p.x, p.y);
    __half2 h1 = __floats2half2_rn(p.z, p.w);
    uint2 u;
    u.x = *reinterpret_cast<unsigned*>(&h0);
    u.y = *reinterpret_cast<unsigned*>(&h1);
    *reinterpret_cast<uint2*>(ph + (size_t)r * SK + 4 * t) = u;
}

// ---------------- residual + bias + LayerNorm (float4) ----------------
__global__ __launch_bounds__(256)
void ln_kernel(const float* __restrict__ y, const float* __restrict__ dec,
               const float* __restrict__ bf, const float* __restrict__ gamma,
               const float* __restrict__ beta, float* __restrict__ out)
{
    const size_t base4 = ((size_t)blockIdx.x * D_) >> 2;
    const int t = threadIdx.x;
    const float4 y4 = reinterpret_cast<const float4*>(y)[base4 + t];
    const float4 d4 = reinterpret_cast<const float4*>(dec)[base4 + t];
    const float4 b4 = reinterpret_cast<const float4*>(bf)[t];
    float4 x;
    x.x = y4.x + b4.x + d4.x;
    x.y = y4.y + b4.y + d4.y;
    x.z = y4.z + b4.z + d4.z;
    x.w = y4.w + b4.w + d4.w;

    float s  = (x.x + x.y) + (x.z + x.w);
    float ss = (x.x * x.x + x.y * x.y) + (x.z * x.z + x.w * x.w);
    s  = blockReduceSum(s);
    ss = blockReduceSum(ss);
    const float mu   = s * (1.0f / D_);
    const float var  = ss * (1.0f / D_) - mu * mu;
    const float rstd = rsqrtf(var + 1e-5f);

    const float4 g4  = reinterpret_cast<const float4*>(gamma)[t];
    const float4 be4 = reinterpret_cast<const float4*>(beta)[t];
    float4 o;
    o.x = (x.x - mu) * rstd * g4.x + be4.x;
    o.y = (x.y - mu) * rstd * g4.y + be4.y;
    o.z = (x.z - mu) * rstd * g4.z + be4.z;
    o.w = (x.w - mu) * rstd * g4.w + be4.w;
    reinterpret_cast<float4*>(out)[base4 + t] = o;
}

// ---------------- launcher ----------------
extern "C" void kernel_launch(void* const* d_in, const int* in_sizes, int n_in,
                              void* d_out, int out_size)
{
    (void)in_sizes; (void)n_in; (void)out_size;
    const float* memory = (const float*)d_in[0];
    const float* dec    = (const float*)d_in[1];
    const float* qmask  = (const float*)d_in[2];
    const float* Wk     = (const float*)d_in[3];
    const float* Wv     = (const float*)d_in[4];
    const float* Wq     = (const float*)d_in[5];
    const float* Wf     = (const float*)d_in[6];
    const float* bf     = (const float*)d_in[7];
    const float* gamma  = (const float*)d_in[8];
    const float* beta   = (const float*)d_in[9];
    const void*  mask   = d_in[10];

    float* out_x = (float*)d_out;
    float* attns = out_x + (size_t)BATCH * SQ * D_;   // x first, then attns

    __half *memH, *cat, *Kh, *Vh, *Qh, *Ph, *Wh;
    float* gY;
    cudaGetSymbolAddress((void**)&memH, g_memH);
    cudaGetSymbolAddress((void**)&cat,  g_cat);
    cudaGetSymbolAddress((void**)&Kh,   g_Kh);
    cudaGetSymbolAddress((void**)&Vh,   g_Vh);
    cudaGetSymbolAddress((void**)&Qh,   g_Qh);
    cudaGetSymbolAddress((void**)&Ph,   g_Ph);
    cudaGetSymbolAddress((void**)&Wh,   g_Wh);
    cudaGetSymbolAddress((void**)&gY,   g_Y);
    __half* Wkh = Wh;
    __half* Wvh = Wh + (size_t)1024 * 1024;
    __half* Wqh = Wh + (size_t)2 * 1024 * 1024;
    __half* Wfh = Wh + (size_t)3 * 1024 * 1024;   // [2048,1024]

    const int smemR = gemm_smem_bytes(false);
    const int smemC = gemm_smem_bytes(true);
    cudaFuncSetAttribute(gemm_h<false, __half>,
                         cudaFuncAttributeMaxDynamicSharedMemorySize, smemR);
    cudaFuncSetAttribute(gemm_h<false, float>,
                         cudaFuncAttributeMaxDynamicSharedMemorySize, smemR);
    cudaFuncSetAttribute(gemm_h<true, float>,
                         cudaFuncAttributeMaxDynamicSharedMemorySize, smemC);

    const dim3 blk(256);
    const long long SqD  = (long long)SQ * D_;
    const long long SkD  = (long long)SK * D_;
    const long long SqSk = (long long)SQ * SK;
    const float inv_sqrt_dh = 0.08838834764831843f;  // 1/sqrt(128)

    // 0) fp32 -> fp16 conversions
    f2h_kernel<<<4096, blk>>>((const float4*)memory, (uint4*)memH, 1048576);
    dec2cat_kernel<<<4096, blk>>>((const float4*)dec, cat);
    f2h_kernel<<<512,  blk>>>((const float4*)Wk, (uint4*)Wkh, 131072);
    f2h_kernel<<<512,  blk>>>((const float4*)Wv, (uint4*)Wvh, 131072);
    f2h_kernel<<<512,  blk>>>((const float4*)Wq, (uint4*)Wqh, 131072);
    f2h_kernel<<<1024, blk>>>((const float4*)Wf, (uint4*)Wfh, 262144);
    detect_mask_kernel<<<1, 256>>>((const unsigned*)mask);

    // 1) projections: [8192,1024] x [1024,1024] -> fp16
    gemm_h<false, __half><<<dim3(8, 64, 1), blk, smemR>>>(
        memH, 0, 0, D_, Wkh, 0, 0, D_, Kh, 0, 0, D_, D_, 1, 1.0f);
    gemm_h<false, __half><<<dim3(8, 64, 1), blk, smemR>>>(
        memH, 0, 0, D_, Wvh, 0, 0, D_, Vh, 0, 0, D_, D_, 1, 1.0f);
    gemm_h<false, __half><<<dim3(8, 64, 1), blk, smemR>>>(
        cat, 0, 0, 2 * D_, Wqh, 0, 0, D_, Qh, 0, 0, D_, D_, 1, 1.0f);

    // 2) scores: per (h,b): S = Q_hb @ K_hb^T / sqrt(dh) -> attns (raw fp32)
    gemm_h<true, float><<<dim3(8, 8, NH * BATCH), blk, smemC>>>(
        Qh, DH, SqD, D_,
        Kh, DH, SkD, D_,
        attns, (long long)BATCH * SqSk, SqSk, SK,
        DH, BATCH, inv_sqrt_dh);

    // 3) masked softmax + query-mask -> fp32 attns (output) + fp16 Ph
    softmax_kernel<<<NH * BATCH * SQ, 256>>>(attns, Ph, mask, qmask);

    // 4) attn @ V: per (h,b): [1024,1024] x [1024,128] -> right half of cat (fp16)
    gemm_h<false, __half><<<dim3(1, 8, NH * BATCH), blk, smemR>>>(
        Ph, (long long)BATCH * SqSk, SqSk, SK,
        Vh, DH, SkD, D_,
        cat + D_, DH, (long long)SQ * 2 * D_, 2 * D_,
        SK, BATCH, 1.0f);

    // 5) Y = cat @ Wf   (K = 2048, fp32 out)
    gemm_h<false, float><<<dim3(8, 64, 1), blk, smemR>>>(
        cat, 0, 0, 2 * D_, Wfh, 0, 0, D_, gY, 0, 0, D_, 2 * D_, 1, 1.0f);

    // 6) residual + bias + LayerNorm -> x output (exact fp32 dec residual)
    ln_kernel<<<BATCH * SQ, 256>>>(gY, dec, bf, gamma, beta, out_x);
}

// round 13
// speedup vs baseline: 4.2813x; 1.0559x over previous
#include <cuda_runtime.h>
#include <cuda_fp16.h>
#include <mma.h>
#include <cstdint>
#include <type_traits>

using namespace nvcuda;

// Problem dims (fixed by the dataset)
#define D_    1024
#define SQ    1024
#define SK    1024
#define BATCH 8
#define NH    8
#define DH    128

#define NEGV  (-4294967295.0f)   // -2^32 + 1

// ---------------- scratch (device globals: no allocation allowed) ----------------
__device__ __half g_memH[(size_t)BATCH * SK * D_];        // fp16(memory)            [8192,1024]
__device__ __half g_cat[(size_t)BATCH * SQ * 2 * D_];     // [fp16(dec) | attn@V]    [8192,2048]
__device__ __half g_Kh[(size_t)BATCH * SK * D_];          // fp16(memory @ Wk)
__device__ __half g_Vh[(size_t)BATCH * SK * D_];          // fp16(memory @ Wv)
__device__ __half g_Qh[(size_t)BATCH * SQ * D_];          // fp16(dec @ Wq)
__device__ __half g_Ph[(size_t)NH * BATCH * SQ * SK];     // fp16(softmax(attn))     128MB
__device__ __half g_Wh[(size_t)5 * 1024 * 1024];          // Wk|Wv|Wq|Wf(2M) fp16
__device__ float  g_Y[(size_t)BATCH * SQ * D_];           // concat @ Wf (fp32)
__device__ int    g_mask_kind;                            // 0=int32, 1=byte, 2=float32

// ---------------- helpers ----------------
__device__ __forceinline__ void cp16(void* smem_dst, const void* gsrc) {
    uint32_t s = (uint32_t)__cvta_generic_to_shared(smem_dst);
    asm volatile("cp.async.cg.shared.global [%0], [%1], 16;\n" :: "r"(s), "l"(gsrc));
}
__device__ __forceinline__ void cp_commit() { asm volatile("cp.async.commit_group;\n"); }
__device__ __forceinline__ void cp_wait2()  { asm volatile("cp.async.wait_group 2;\n"); }

// ---------------- reductions ----------------
__device__ __forceinline__ float blockReduceSum(float v) {
    __shared__ float sh[8];
    __syncthreads();
    #pragma unroll
    for (int o = 16; o > 0; o >>= 1) v += __shfl_xor_sync(0xffffffffu, v, o);
    int lane = threadIdx.x & 31, w = threadIdx.x >> 5;
    if (lane == 0) sh[w] = v;
    __syncthreads();
    if (w == 0) {
        float x = (lane < 8) ? sh[lane] : 0.0f;
        #pragma unroll
        for (int o = 4; o > 0; o >>= 1) x += __shfl_xor_sync(0xffffffffu, x, o);
        if (lane == 0) sh[0] = x;
    }
    __syncthreads();
    return sh[0];
}
__device__ __forceinline__ float blockReduceMax(float v) {
    __shared__ float sh[8];
    __syncthreads();
    #pragma unroll
    for (int o = 16; o > 0; o >>= 1) v = fmaxf(v, __shfl_xor_sync(0xffffffffu, v, o));
    int lane = threadIdx.x & 31, w = threadIdx.x >> 5;
    if (lane == 0) sh[w] = v;
    __syncthreads();
    if (w == 0) {
        float x = (lane < 8) ? sh[lane] : -3.4e38f;
        #pragma unroll
        for (int o = 4; o > 0; o >>= 1) x = fmaxf(x, __shfl_xor_sync(0xffffffffu, x, o));
        if (lane == 0) sh[0] = x;
    }
    __syncthreads();
    return sh[0];
}

// ---------------- fp32 -> fp16 conversion (8 elems/thread, 16B stores) ----------------
__global__ __launch_bounds__(256)
void f2h_kernel(const float4* __restrict__ in, uint4* __restrict__ out, int n8)
{
    int i = blockIdx.x * 256 + threadIdx.x;
    if (i < n8) {
        float4 a = in[2 * i], b = in[2 * i + 1];
        __half2 h0 = __floats2half2_rn(a.x, a.y);
        __half2 h1 = __floats2half2_rn(a.z, a.w);
        __half2 h2 = __floats2half2_rn(b.x, b.y);
        __half2 h3 = __floats2half2_rn(b.z, b.w);
        uint4 u;
        u.x = *reinterpret_cast<unsigned*>(&h0);
        u.y = *reinterpret_cast<unsigned*>(&h1);
        u.z = *reinterpret_cast<unsigned*>(&h2);
        u.w = *reinterpret_cast<unsigned*>(&h3);
        out[i] = u;
    }
}

// dec fp32 [8192,1024] -> fp16 into left half of cat [8192,2048]
__global__ __launch_bounds__(256)
void dec2cat_kernel(const float4* __restrict__ dec, __half* __restrict__ cat)
{
    int i = blockIdx.x * 256 + threadIdx.x;     // 1M threads, 8 elems each
    int row = i >> 7, c8 = i & 127;
    float4 a = dec[2 * i], b = dec[2 * i + 1];
    __half2 h0 = __floats2half2_rn(a.x, a.y);
    __half2 h1 = __floats2half2_rn(a.z, a.w);
    __half2 h2 = __floats2half2_rn(b.x, b.y);
    __half2 h3 = __floats2half2_rn(b.z, b.w);
    uint4 u;
    u.x = *reinterpret_cast<unsigned*>(&h0);
    u.y = *reinterpret_cast<unsigned*>(&h1);
    u.z = *reinterpret_cast<unsigned*>(&h2);
    u.w = *reinterpret_cast<unsigned*>(&h3);
    *reinterpret_cast<uint4*>(cat + (size_t)row * 2048 + c8 * 8) = u;
}

// ---------------- generic batched fp16 wmma GEMM ----------------
// 128 threads / 4 warps, BM=BN=128, warp tile 64x64 (4x4 fragments).
// C[z][M,N] = alpha * A[z][M,K] * B[z][K,N], fp32 accumulate.
// A row-major fp16. B row-major fp16 if !BCOL, else B(k,n)=Bptr[n*ldb+k].
// OutT = float (direct store) or __half (round epilogue).
// Requires: M%128==0, N%128==0, K%32==0, K/32 >= 3, 16B-aligned pointers & lds.

#define BM 128
#define BN 128
#define BK 32
#define APADh  40    // halfs: 80B row stride (16B multiple)
#define BNPADh 136   // halfs: 272B row stride (16B multiple)
#define NST 3

template<bool BCOL, typename OutT>
__global__ __launch_bounds__(128, 2)
void gemm_h(const __half* __restrict__ Abase, long long sA1, long long sA2, int lda,
            const __half* __restrict__ Bbase, long long sB1, long long sB2, int ldb,
            OutT*         __restrict__ Cbase, long long sC1, long long sC2, int ldc,
            int K, int Z2, float alpha)
{
    extern __shared__ __align__(16) __half smh[];
    constexpr int ASTG = BM * APADh;                        // 5120 halfs
    constexpr int BSTG = BCOL ? (BM * APADh) : (BK * BNPADh);
    __half* As = smh;
    __half* Bs = smh + NST * ASTG;

    const int z  = blockIdx.z;
    const int z1 = z / Z2, z2 = z % Z2;
    const __half* A = Abase + (size_t)z1 * sA1 + (size_t)z2 * sA2;
    const __half* B = Bbase + (size_t)z1 * sB1 + (size_t)z2 * sB2;
    OutT*         C = Cbase + (size_t)z1 * sC1 + (size_t)z2 * sC2;

    const int m0 = blockIdx.y * BM;
    const int n0 = blockIdx.x * BN;

    const int tid    = threadIdx.x;
    const int wid    = tid >> 5;
    const int warp_m = wid & 1;   // 2 warps along M (64 rows each)
    const int warp_n = wid >> 1;  // 2 warps along N (64 cols each)

    wmma::fragment<wmma::accumulator, 16, 16, 16, float> c[4][4];
    #pragma unroll
    for (int mi = 0; mi < 4; mi++)
        #pragma unroll
        for (int ni = 0; ni < 4; ni++)
            wmma::fill_fragment(c[mi][ni], 0.0f);

    auto stage = [&](int it) {
        const int buf = it % NST;
        const int k0  = it * BK;
        __half* as = As + buf * ASTG;
        #pragma unroll
        for (int i = 0; i < 4; i++) {           // A: 512 chunks (128 rows x 4x16B)
            int ch  = tid + i * 128;
            int row = ch >> 2;
            int c8  = ch & 3;
            cp16(as + row * APADh + c8 * 8,
                 A + (size_t)(m0 + row) * lda + k0 + c8 * 8);
        }
        __half* bs = Bs + buf * BSTG;
        if (BCOL) {
            #pragma unroll
            for (int i = 0; i < 4; i++) {       // Bs[n][k]: 128 rows x 4x16B
                int ch  = tid + i * 128;
                int row = ch >> 2;
                int c8  = ch & 3;
                cp16(bs + row * APADh + c8 * 8,
                     B + (size_t)(n0 + row) * ldb + k0 + c8 * 8);
            }
        } else {
            #pragma unroll
            for (int i = 0; i < 4; i++) {       // Bs[k][n]: 32 rows x 16x16B
                int ch  = tid + i * 128;
                int row = ch >> 4;
                int c8  = ch & 15;
                cp16(bs + row * BNPADh + c8 * 8,
                     B + (size_t)(k0 + row) * ldb + n0 + c8 * 8);
            }
        }
    };

    const int T = K / BK;       // >= 3 for all our GEMMs (min K = 128)
    stage(0); cp_commit();
    stage(1); cp_commit();

    for (int it = 0; it < T; it++) {
        if (it + 2 < T) stage(it + 2);
        cp_commit();                 // unconditional: keeps group accounting aligned
        cp_wait2();                  // slab `it` fully landed
        __syncthreads();

        const __half* as = As + (it % NST) * ASTG;
        const __half* bs = Bs + (it % NST) * BSTG;

        #pragma unroll
        for (int kk = 0; kk < BK; kk += 16) {
            wmma::fragment<wmma::matrix_a, 16, 16, 16, __half, wmma::row_major> a[4];
            #pragma unroll
            for (int mi = 0; mi < 4; mi++)
                wmma::load_matrix_sync(a[mi], as + (warp_m * 64 + mi * 16) * APADh + kk, APADh);
            if (BCOL) {
                wmma::fragment<wmma::matrix_b, 16, 16, 16, __half, wmma::col_major> b[4];
                #pragma unroll
                for (int ni = 0; ni < 4; ni++)
                    wmma::load_matrix_sync(b[ni], bs + (warp_n * 64 + ni * 16) * APADh + kk, APADh);
                #pragma unroll
                for (int mi = 0; mi < 4; mi++)
                    #pragma unroll
                    for (int ni = 0; ni < 4; ni++)
                        wmma::mma_sync(c[mi][ni], a[mi], b[ni], c[mi][ni]);
            } else {
                wmma::fragment<wmma::matrix_b, 16, 16, 16, __half, wmma::row_major> b[4];
                #pragma unroll
                for (int ni = 0; ni < 4; ni++)
                    wmma::load_matrix_sync(b[ni], bs + kk * BNPADh + warp_n * 64 + ni * 16, BNPADh);
                #pragma unroll
                for (int mi = 0; mi < 4; mi++)
                    #pragma unroll
                    for (int ni = 0; ni < 4; ni++)
                        wmma::mma_sync(c[mi][ni], a[mi], b[ni], c[mi][ni]);
            }
        }
        __syncthreads();
    }

    // --- epilogue ---
    #pragma unroll
    for (int mi = 0; mi < 4; mi++) {
        #pragma unroll
        for (int ni = 0; ni < 4; ni++) {
            OutT* Cp = C + (size_t)(m0 + warp_m * 64 + mi * 16) * ldc
                         + n0 + warp_n * 64 + ni * 16;
            if constexpr (std::is_same<OutT, float>::value) {
                #pragma unroll
                for (int t = 0; t < c[mi][ni].num_elements; t++)
                    c[mi][ni].x[t] *= alpha;
                wmma::store_matrix_sync(Cp, c[mi][ni], ldc, wmma::mem_row_major);
            } else {
                wmma::fragment<wmma::accumulator, 16, 16, 16, __half> hc;
                #pragma unroll
                for (int t = 0; t < hc.num_elements; t++)
                    hc.x[t] = __float2half(c[mi][ni].x[t] * alpha);
                wmma::store_matrix_sync(Cp, hc, ldc, wmma::mem_row_major);
            }
        }
    }
}

static inline int gemm_smem_bytes(bool bcol) {
    int astg = BM * APADh;
    int bstg = bcol ? (BM * APADh) : (BK * BNPADh);
    return (int)(NST * (astg + bstg) * sizeof(__half));
}

// ---------------- mask dtype detection ----------------
__global__ void detect_mask_kernel(const unsigned* __restrict__ m) {
    __shared__ int votes[2];  // [0]=byte, [1]=float
    if (threadIdx.x < 2) votes[threadIdx.x] = 0;
    __syncthreads();
    for (int i = threadIdx.x; i < 2048; i += blockDim.x) {
        unsigned w = m[i];
        if (w > 1u) {
            if (w == 0x3F800000u) atomicOr(&votes[1], 1);
            else                  atomicOr(&votes[0], 1);
        }
    }
    __syncthreads();
    if (threadIdx.x == 0)
        g_mask_kind = votes[0] ? 1 : (votes[1] ? 2 : 0);
}

// ---------------- masked softmax + query-mask ----------------
// Reads raw fp32 scores from attns, writes fp32 attns (output) + fp16 copy for GEMM.
__global__ __launch_bounds__(256)
void softmax_kernel(float* __restrict__ attns, __half* __restrict__ ph,
                    const void* __restrict__ mask,
                    const float* __restrict__ qmask)
{
    const int r  = blockIdx.x;           // 0 .. 64*1024-1
    const int q  = r & (SQ - 1);
    const int hb = r >> 10;
    const int b  = hb & (BATCH - 1);
    float4* row4 = reinterpret_cast<float4*>(attns + (size_t)r * SK);
    const size_t m4 = (((size_t)b * SQ + q) * (size_t)SK) >> 2;
    const int t = threadIdx.x;
    const int kind = g_mask_kind;

    float4 v = row4[t];
    if (kind == 0) {
        int4 m = reinterpret_cast<const int4*>(mask)[m4 + t];
        if (m.x) v.x = NEGV;
        if (m.y) v.y = NEGV;
        if (m.z) v.z = NEGV;
        if (m.w) v.w = NEGV;
    } else if (kind == 1) {
        uchar4 m = reinterpret_cast<const uchar4*>(mask)[m4 + t];
        if (m.x) v.x = NEGV;
        if (m.y) v.y = NEGV;
        if (m.z) v.z = NEGV;
        if (m.w) v.w = NEGV;
    } else {
        float4 m = reinterpret_cast<const float4*>(mask)[m4 + t];
        if (m.x != 0.0f) v.x = NEGV;
        if (m.y != 0.0f) v.y = NEGV;
        if (m.z != 0.0f) v.z = NEGV;
        if (m.w != 0.0f) v.w = NEGV;
    }

    float mx = fmaxf(fmaxf(v.x, v.y), fmaxf(v.z, v.w));
    mx = blockReduceMax(mx);

    float4 p;
    p.x = __expf(v.x - mx);
    p.y = __expf(v.y - mx);
    p.z = __expf(v.z - mx);
    p.w = __expf(v.w - mx);
    float s = (p.x + p.y) + (p.z + p.w);
    s = blockReduceSum(s);

    const float scale = qmask[b * SQ + q] / s;
    p.x *= scale; p.y *= scale; p.z *= scale; p.w *= scale;
    row4[t] = p;

    __half2 h0 = __floats2half2_rn(p.x, p.y);
    __half2 h1 = __floats2half2_rn(p.z, p.w);
    uint2 u;
    u.x = *reinterpret_cast<unsigned*>(&h0);
    u.y = *reinterpret_cast<unsigned*>(&h1);
    *reinterpret_cast<uint2*>(ph + (size_t)r * SK + 4 * t) = u;
}

// ---------------- residual + bias + LayerNorm (float4) ----------------
__global__ __launch_bounds__(256)
void ln_kernel(const float* __restrict__ y, const float* __restrict__ dec,
               const float* __restrict__ bf, const float* __restrict__ gamma,
               const float* __restrict__ beta, float* __restrict__ out)
{
    const size_t base4 = ((size_t)blockIdx.x * D_) >> 2;
    const int t = threadIdx.x;
    const float4 y4 = reinterpret_cast<const float4*>(y)[base4 + t];
    const float4 d4 = reinterpret_cast<const float4*>(dec)[base4 + t];
    const float4 b4 = reinterpret_cast<const float4*>(bf)[t];
    float4 x;
    x.x = y4.x + b4.x + d4.x;
    x.y = y4.y + b4.y + d4.y;
    x.z = y4.z + b4.z + d4.z;
    x.w = y4.w + b4.w + d4.w;

    float s  = (x.x + x.y) + (x.z + x.w);
    float ss = (x.x * x.x + x.y * x.y) + (x.z * x.z + x.w * x.w);
    s  = blockReduceSum(s);
    ss = blockReduceSum(ss);
    const float mu   = s * (1.0f / D_);
    const float var  = ss * (1.0f / D_) - mu * mu;
    const float rstd = rsqrtf(var + 1e-5f);

    const float4 g4  = reinterpret_cast<const float4*>(gamma)[t];
    const float4 be4 = reinterpret_cast<const float4*>(beta)[t];
    float4 o;
    o.x = (x.x - mu) * rstd * g4.x + be4.x;
    o.y = (x.y - mu) * rstd * g4.y + be4.y;
    o.z = (x.z - mu) * rstd * g4.z + be4.z;
    o.w = (x.w - mu) * rstd * g4.w + be4.w;
    reinterpret_cast<float4*>(out)[base4 + t] = o;
}

// ---------------- launcher ----------------
extern "C" void kernel_launch(void* const* d_in, const int* in_sizes, int n_in,
                              void* d_out, int out_size)
{
    (void)in_sizes; (void)n_in; (void)out_size;
    const float* memory = (const float*)d_in[0];
    const float* dec    = (const float*)d_in[1];
    const float* qmask  = (const float*)d_in[2];
    const float* Wk     = (const float*)d_in[3];
    const float* Wv     = (const float*)d_in[4];
    const float* Wq     = (const float*)d_in[5];
    const float* Wf     = (const float*)d_in[6];
    const float* bf     = (const float*)d_in[7];
    const float* gamma  = (const float*)d_in[8];
    const float* beta   = (const float*)d_in[9];
    const void*  mask   = d_in[10];

    float* out_x = (float*)d_out;
    float* attns = out_x + (size_t)BATCH * SQ * D_;   // x first, then attns

    __half *memH, *cat, *Kh, *Vh, *Qh, *Ph, *Wh;
    float* gY;
    cudaGetSymbolAddress((void**)&memH, g_memH);
    cudaGetSymbolAddress((void**)&cat,  g_cat);
    cudaGetSymbolAddress((void**)&Kh,   g_Kh);
    cudaGetSymbolAddress((void**)&Vh,   g_Vh);
    cudaGetSymbolAddress((void**)&Qh,   g_Qh);
    cudaGetSymbolAddress((void**)&Ph,   g_Ph);
    cudaGetSymbolAddress((void**)&Wh,   g_Wh);
    cudaGetSymbolAddress((void**)&gY,   g_Y);
    __half* Wkh = Wh;
    __half* Wvh = Wh + (size_t)1024 * 1024;
    __half* Wqh = Wh + (size_t)2 * 1024 * 1024;
    __half* Wfh = Wh + (size_t)3 * 1024 * 1024;   // [2048,1024]

    const int smemR = gemm_smem_bytes(false);
    const int smemC = gemm_smem_bytes(true);
    cudaFuncSetAttribute(gemm_h<false, __half>,
                         cudaFuncAttributeMaxDynamicSharedMemorySize, smemR);
    cudaFuncSetAttribute(gemm_h<false, float>,
                         cudaFuncAttributeMaxDynamicSharedMemorySize, smemR);
    cudaFuncSetAttribute(gemm_h<true, float>,
                         cudaFuncAttributeMaxDynamicSharedMemorySize, smemC);

    const dim3 blk(256);
    const dim3 gblk(128);
    const long long SqD  = (long long)SQ * D_;
    const long long SkD  = (long long)SK * D_;
    const long long SqSk = (long long)SQ * SK;
    const float inv_sqrt_dh = 0.08838834764831843f;  // 1/sqrt(128)

    // 0) fp32 -> fp16 conversions
    f2h_kernel<<<4096, blk>>>((const float4*)memory, (uint4*)memH, 1048576);
    dec2cat_kernel<<<4096, blk>>>((const float4*)dec, cat);
    f2h_kernel<<<512,  blk>>>((const float4*)Wk, (uint4*)Wkh, 131072);
    f2h_kernel<<<512,  blk>>>((const float4*)Wv, (uint4*)Wvh, 131072);
    f2h_kernel<<<512,  blk>>>((const float4*)Wq, (uint4*)Wqh, 131072);
    f2h_kernel<<<1024, blk>>>((const float4*)Wf, (uint4*)Wfh, 262144);
    detect_mask_kernel<<<1, 256>>>((const unsigned*)mask);

    // 1) projections: [8192,1024] x [1024,1024] -> fp16
    gemm_h<false, __half><<<dim3(8, 64, 1), gblk, smemR>>>(
        memH, 0, 0, D_, Wkh, 0, 0, D_, Kh, 0, 0, D_, D_, 1, 1.0f);
    gemm_h<false, __half><<<dim3(8, 64, 1), gblk, smemR>>>(
        memH, 0, 0, D_, Wvh, 0, 0, D_, Vh, 0, 0, D_, D_, 1, 1.0f);
    gemm_h<false, __half><<<dim3(8, 64, 1), gblk, smemR>>>(
        cat, 0, 0, 2 * D_, Wqh, 0, 0, D_, Qh, 0, 0, D_, D_, 1, 1.0f);

    // 2) scores: per (h,b): S = Q_hb @ K_hb^T / sqrt(dh) -> attns (raw fp32)
    gemm_h<true, float><<<dim3(8, 8, NH * BATCH), gblk, smemC>>>(
        Qh, DH, SqD, D_,
        Kh, DH, SkD, D_,
        attns, (long long)BATCH * SqSk, SqSk, SK,
        DH, BATCH, inv_sqrt_dh);

    // 3) masked softmax + query-mask -> fp32 attns (output) + fp16 Ph
    softmax_kernel<<<NH * BATCH * SQ, 256>>>(attns, Ph, mask, qmask);

    // 4) attn @ V: per (h,b): [1024,1024] x [1024,128] -> right half of cat (fp16)
    gemm_h<false, __half><<<dim3(1, 8, NH * BATCH), gblk, smemR>>>(
        Ph, (long long)BATCH * SqSk, SqSk, SK,
        Vh, DH, SkD, D_,
        cat + D_, DH, (long long)SQ * 2 * D_, 2 * D_,
        SK, BATCH, 1.0f);

    // 5) Y = cat @ Wf   (K = 2048, fp32 out)
    gemm_h<false, float><<<dim3(8, 64, 1), gblk, smemR>>>(
        cat, 0, 0, 2 * D_, Wfh, 0, 0, D_, gY, 0, 0, D_, 2 * D_, 1, 1.0f);

    // 6) residual + bias + LayerNorm -> x output (exact fp32 dec residual)
    ln_kernel<<<BATCH * SQ, 256>>>(gY, dec, bf, gamma, beta, out_x);
}